// round 1
// baseline (speedup 1.0000x reference)
#include <cuda_runtime.h>
#include <math.h>

#define NNODES 50000
#define EMAX   850048
#define DIM    256
#define HEADS  4
#define HIDD   64
#define COUT   32

// ---------------- scratch (device globals; no allocation allowed) ----------------
__device__ __align__(128) float g_f  [NNODES * DIM];   // projected features current layer
__device__ __align__(128) float g_h0 [NNODES * DIM];   // layer0 output (residual for layer1)
__device__ __align__(128) float g_h1 [NNODES * DIM];   // layer1 output
__device__ __align__(128) float g_rst[NNODES * DIM];   // aggregation accumulator
__device__ __align__(128) float g_e  [(size_t)EMAX * HEADS]; // edge scores / exp values
__device__ __align__(128) float g_m  [NNODES * HEADS]; // segment max
__device__ __align__(128) float g_z  [NNODES * HEADS]; // segment sum
__device__ __align__(128) float g_f2 [NNODES * COUT];  // layer2 projection
__device__ __align__(128) float g_r2 [NNODES * COUT];  // layer2 residual (h1 @ Wres2)

// ---------------- helpers ----------------
__device__ __forceinline__ float atomicMaxF(float* addr, float value) {
    if (value >= 0.f) {
        return __int_as_float(atomicMax((int*)addr, __float_as_int(value)));
    } else {
        return __uint_as_float(atomicMin((unsigned int*)addr, __float_as_uint(value)));
    }
}

__device__ __forceinline__ void redAddV4(float* p, float a, float b, float c, float d) {
    asm volatile("red.global.add.v4.f32 [%0], {%1,%2,%3,%4};"
                 :: "l"(p), "f"(a), "f"(b), "f"(c), "f"(d) : "memory");
}

// ---------------- SGEMM: C[M,Nc] = A[M,K] * B[K,Nc] ----------------
// 64x64 block tile, 16 K-tile, 256 threads, 4x4 microtile.
__global__ void sgemm_kernel(const float* __restrict__ A, const float* __restrict__ B,
                             float* __restrict__ C, int M, int K, int Nc) {
    __shared__ float As[16][64];
    __shared__ float Bs[16][64];
    const int tx = threadIdx.x & 15;   // 0..15 -> col group
    const int ty = threadIdx.x >> 4;   // 0..15 -> row group
    const int rowBase = blockIdx.y * 64;
    const int colBase = blockIdx.x * 64;

    float acc[4][4] = {};

    for (int k0 = 0; k0 < K; k0 += 16) {
        for (int i = threadIdx.x; i < 64 * 16; i += 256) {
            int mm = i >> 4, kk = i & 15;
            int gr = rowBase + mm;
            As[kk][mm] = (gr < M) ? A[(size_t)gr * K + k0 + kk] : 0.f;
        }
        for (int i = threadIdx.x; i < 16 * 64; i += 256) {
            int kk = i >> 6, nn = i & 63;
            int gc = colBase + nn;
            Bs[kk][nn] = (gc < Nc) ? B[(size_t)(k0 + kk) * Nc + gc] : 0.f;
        }
        __syncthreads();
        #pragma unroll
        for (int kk = 0; kk < 16; kk++) {
            float a[4], b[4];
            #pragma unroll
            for (int i = 0; i < 4; i++) a[i] = As[kk][ty * 4 + i];
            #pragma unroll
            for (int j = 0; j < 4; j++) b[j] = Bs[kk][tx * 4 + j];
            #pragma unroll
            for (int i = 0; i < 4; i++)
                #pragma unroll
                for (int j = 0; j < 4; j++)
                    acc[i][j] += a[i] * b[j];
        }
        __syncthreads();
    }
    #pragma unroll
    for (int i = 0; i < 4; i++) {
        int r = rowBase + ty * 4 + i;
        if (r >= M) continue;
        #pragma unroll
        for (int j = 0; j < 4; j++) {
            int c = colBase + tx * 4 + j;
            if (c < Nc) C[(size_t)r * Nc + c] = acc[i][j];
        }
    }
}

// ---------------- init: m = -inf, z = 0, rst = 0 ----------------
__global__ void init_layer(float* __restrict__ m, float* __restrict__ z,
                           float* __restrict__ rst, int nm, int nr) {
    int i = blockIdx.x * blockDim.x + threadIdx.x;
    if (i < nm) { m[i] = __int_as_float(0xff800000); z[i] = 0.f; }
    if (i < nr) rst[i] = 0.f;
}

// ---------------- edge scores (H=4, D=64): warp per edge ----------------
// e[edge,h] = sum_d leakyrelu(f[src,h,d] + f[dst,h,d]) * a[h,d];  atomicMax into m.
__global__ void edge_scores(const float* __restrict__ f, const int* __restrict__ src,
                            const int* __restrict__ dst, const float* __restrict__ a,
                            float* __restrict__ e, float* __restrict__ m, int E) {
    __shared__ float sa[256];
    if (threadIdx.x < 256) sa[threadIdx.x] = a[threadIdx.x];
    __syncthreads();
    int warp = (blockIdx.x * blockDim.x + threadIdx.x) >> 5;
    int lane = threadIdx.x & 31;
    if (warp >= E) return;
    int s = src[warp], d = dst[warp];
    int base = lane * 8;                 // lane covers 8 contiguous dims; head = lane>>3
    const float4* fs = reinterpret_cast<const float4*>(f + (size_t)s * DIM + base);
    const float4* fd = reinterpret_cast<const float4*>(f + (size_t)d * DIM + base);
    float4 x0 = fs[0], x1 = fs[1];
    float4 y0 = fd[0], y1 = fd[1];
    float v[8] = { x0.x + y0.x, x0.y + y0.y, x0.z + y0.z, x0.w + y0.w,
                   x1.x + y1.x, x1.y + y1.y, x1.z + y1.z, x1.w + y1.w };
    float p = 0.f;
    #pragma unroll
    for (int j = 0; j < 8; j++) {
        float t = v[j];
        float lv = t > 0.f ? t : 0.2f * t;
        p += lv * sa[base + j];
    }
    p += __shfl_xor_sync(0xffffffffu, p, 1);
    p += __shfl_xor_sync(0xffffffffu, p, 2);
    p += __shfl_xor_sync(0xffffffffu, p, 4);
    if ((lane & 7) == 0) {
        int head = lane >> 3;
        e[(size_t)warp * HEADS + head] = p;
        atomicMaxF(&m[d * HEADS + head], p);
    }
}

// ---------------- exp + segment sum (H=4) ----------------
__global__ void edge_exp(float* __restrict__ e, const int* __restrict__ dst,
                         const float* __restrict__ m, float* __restrict__ z, int E) {
    int i = blockIdx.x * blockDim.x + threadIdx.x;
    if (i >= E * HEADS) return;
    int edge = i >> 2, h = i & 3;
    int d = dst[edge];
    float ex = __expf(e[i] - m[d * HEADS + h]);
    e[i] = ex;
    atomicAdd(&z[d * HEADS + h], ex);
}

// ---------------- weighted aggregate (H=4): warp per edge ----------------
__global__ void edge_agg(const float* __restrict__ f, const int* __restrict__ src,
                         const int* __restrict__ dst, const float* __restrict__ ex,
                         const float* __restrict__ z, float* __restrict__ rst, int E) {
    int warp = (blockIdx.x * blockDim.x + threadIdx.x) >> 5;
    int lane = threadIdx.x & 31;
    if (warp >= E) return;
    int s = src[warp], d = dst[warp];
    int head = lane >> 3;
    float alpha = ex[(size_t)warp * HEADS + head] / z[d * HEADS + head];
    int base = lane * 8;
    const float4* fs = reinterpret_cast<const float4*>(f + (size_t)s * DIM + base);
    float4 x0 = fs[0], x1 = fs[1];
    float* out = rst + (size_t)d * DIM + base;
    redAddV4(out,     alpha * x0.x, alpha * x0.y, alpha * x0.z, alpha * x0.w);
    redAddV4(out + 4, alpha * x1.x, alpha * x1.y, alpha * x1.z, alpha * x1.w);
}

// ---------------- elu(rst [+ res]) ----------------
__global__ void finalize_elu(const float* __restrict__ rst, const float* __restrict__ res,
                             float* __restrict__ out, int n) {
    int i = blockIdx.x * blockDim.x + threadIdx.x;
    if (i >= n) return;
    float v = rst[i] + (res ? res[i] : 0.f);
    out[i] = v > 0.f ? v : expm1f(v);
}

// ---------------- layer2 (H=1, D=32) edge kernels ----------------
__global__ void edge_scores2(const float* __restrict__ f2, const int* __restrict__ src,
                             const int* __restrict__ dst, const float* __restrict__ a,
                             float* __restrict__ e, float* __restrict__ m, int E) {
    __shared__ float sa[32];
    if (threadIdx.x < 32) sa[threadIdx.x] = a[threadIdx.x];
    __syncthreads();
    int warp = (blockIdx.x * blockDim.x + threadIdx.x) >> 5;
    int lane = threadIdx.x & 31;
    if (warp >= E) return;
    int s = src[warp], d = dst[warp];
    float v = f2[(size_t)s * COUT + lane] + f2[(size_t)d * COUT + lane];
    float lv = v > 0.f ? v : 0.2f * v;
    float p = lv * sa[lane];
    p += __shfl_xor_sync(0xffffffffu, p, 1);
    p += __shfl_xor_sync(0xffffffffu, p, 2);
    p += __shfl_xor_sync(0xffffffffu, p, 4);
    p += __shfl_xor_sync(0xffffffffu, p, 8);
    p += __shfl_xor_sync(0xffffffffu, p, 16);
    if (lane == 0) {
        e[warp] = p;
        atomicMaxF(&m[d], p);
    }
}

__global__ void edge_exp2(float* __restrict__ e, const int* __restrict__ dst,
                          const float* __restrict__ m, float* __restrict__ z, int E) {
    int i = blockIdx.x * blockDim.x + threadIdx.x;
    if (i >= E) return;
    int d = dst[i];
    float ex = __expf(e[i] - m[d]);
    e[i] = ex;
    atomicAdd(&z[d], ex);
}

__global__ void edge_agg2(const float* __restrict__ f2, const int* __restrict__ src,
                          const int* __restrict__ dst, const float* __restrict__ ex,
                          const float* __restrict__ z, float* __restrict__ rst, int E) {
    int i = blockIdx.x * blockDim.x + threadIdx.x;
    if (i >= E * 8) return;
    int edge = i >> 3, j = i & 7;   // 8 float4 per edge (32 floats)
    int s = src[edge], d = dst[edge];
    float alpha = ex[edge] / z[d];
    float4 v = reinterpret_cast<const float4*>(f2 + (size_t)s * COUT)[j];
    redAddV4(rst + (size_t)d * COUT + j * 4,
             alpha * v.x, alpha * v.y, alpha * v.z, alpha * v.w);
}

__global__ void final_out(const float* __restrict__ rst, const float* __restrict__ res,
                          float* __restrict__ out, int n) {
    int i = blockIdx.x * blockDim.x + threadIdx.x;
    if (i >= n) return;
    out[i] = rst[i] + res[i];
}

// ---------------- host ----------------
extern "C" void kernel_launch(void* const* d_in, const int* in_sizes, int n_in,
                              void* d_out, int out_size) {
    const float* x     = (const float*)d_in[0];
    const int*   src   = (const int*)  d_in[1];
    const int*   dst   = (const int*)  d_in[2];
    const float* W0    = (const float*)d_in[3];
    const float* a0    = (const float*)d_in[4];
    const float* W1    = (const float*)d_in[5];
    const float* a1    = (const float*)d_in[6];
    const float* W2    = (const float*)d_in[7];
    const float* a2    = (const float*)d_in[8];
    const float* Wres2 = (const float*)d_in[9];
    int E = in_sizes[1];
    if (E > EMAX) E = EMAX;

    float *f, *h0, *h1, *rst, *e, *m, *z, *f2, *r2;
    cudaGetSymbolAddress((void**)&f,   g_f);
    cudaGetSymbolAddress((void**)&h0,  g_h0);
    cudaGetSymbolAddress((void**)&h1,  g_h1);
    cudaGetSymbolAddress((void**)&rst, g_rst);
    cudaGetSymbolAddress((void**)&e,   g_e);
    cudaGetSymbolAddress((void**)&m,   g_m);
    cudaGetSymbolAddress((void**)&z,   g_z);
    cudaGetSymbolAddress((void**)&f2,  g_f2);
    cudaGetSymbolAddress((void**)&r2,  g_r2);

    const int TPB = 256;
    dim3 gemmGrid(DIM / 64, (NNODES + 63) / 64);
    dim3 gemmGrid2((COUT + 63) / 64, (NNODES + 63) / 64);
    int initBlocks  = (NNODES * DIM + TPB - 1) / TPB;
    int edgeWarpBlk = (E * 32 + TPB - 1) / TPB;       // warp per edge
    int expBlocks   = (E * HEADS + TPB - 1) / TPB;

    // ---- layer 0 ----
    sgemm_kernel<<<gemmGrid, TPB>>>(x, W0, f, NNODES, DIM, DIM);
    init_layer<<<initBlocks, TPB>>>(m, z, rst, NNODES * HEADS, NNODES * DIM);
    edge_scores<<<edgeWarpBlk, TPB>>>(f, src, dst, a0, e, m, E);
    edge_exp<<<expBlocks, TPB>>>(e, dst, m, z, E);
    edge_agg<<<edgeWarpBlk, TPB>>>(f, src, dst, e, z, rst, E);
    finalize_elu<<<initBlocks, TPB>>>(rst, nullptr, h0, NNODES * DIM);

    // ---- layer 1 ----
    sgemm_kernel<<<gemmGrid, TPB>>>(h0, W1, f, NNODES, DIM, DIM);
    init_layer<<<initBlocks, TPB>>>(m, z, rst, NNODES * HEADS, NNODES * DIM);
    edge_scores<<<edgeWarpBlk, TPB>>>(f, src, dst, a1, e, m, E);
    edge_exp<<<expBlocks, TPB>>>(e, dst, m, z, E);
    edge_agg<<<edgeWarpBlk, TPB>>>(f, src, dst, e, z, rst, E);
    finalize_elu<<<initBlocks, TPB>>>(rst, h0, h1, NNODES * DIM);

    // ---- layer 2 (1 head, 32 out) ----
    sgemm_kernel<<<gemmGrid2, TPB>>>(h1, W2,    f2, NNODES, DIM, COUT);
    sgemm_kernel<<<gemmGrid2, TPB>>>(h1, Wres2, r2, NNODES, DIM, COUT);
    int init2Blocks = (NNODES * COUT + TPB - 1) / TPB;
    init_layer<<<init2Blocks, TPB>>>(m, z, rst, NNODES, NNODES * COUT);
    edge_scores2<<<edgeWarpBlk, TPB>>>(f2, src, dst, a2, e, m, E);
    edge_exp2<<<(E + TPB - 1) / TPB, TPB>>>(e, dst, m, z, E);
    edge_agg2<<<(E * 8 + TPB - 1) / TPB, TPB>>>(f2, src, dst, e, z, rst, E);
    final_out<<<init2Blocks, TPB>>>(rst, r2, (float*)d_out, NNODES * COUT);
}

// round 2
// speedup vs baseline: 2.9137x; 2.9137x over previous
#include <cuda_runtime.h>
#include <math.h>

#define NNODES 50000
#define EMAX   850048
#define DIM    256
#define HEADS  4
#define COUT   32
#define NEGINF __int_as_float(0xff800000)

// ---------------- scratch (device globals; no allocation allowed) ----------------
__device__ __align__(128) float g_f  [NNODES * DIM];   // projected features current layer
__device__ __align__(128) float g_h0 [NNODES * DIM];   // layer0 output
__device__ __align__(128) float g_h1 [NNODES * DIM];   // layer1 output
__device__ __align__(128) float g_f2 [NNODES * COUT];  // layer2 projection
__device__ __align__(128) float g_r2 [NNODES * COUT];  // layer2 residual
__device__ __align__(128) int   g_deg [NNODES];
__device__ __align__(128) int   g_fill[NNODES];
__device__ __align__(128) int   g_tmp [NNODES];        // inclusive scan partial
__device__ __align__(128) int   g_bsum[256];
__device__ __align__(128) int   g_rowptr[NNODES + 1];
__device__ __align__(128) int   g_csrc[EMAX];

// ================= CSR build =================
__global__ void zero_ints(int* __restrict__ a, int* __restrict__ b, int n) {
    int i = blockIdx.x * blockDim.x + threadIdx.x;
    if (i < n) { a[i] = 0; b[i] = 0; }
}

__global__ void hist_deg(const int* __restrict__ dst, int* __restrict__ deg, int E) {
    int i = blockIdx.x * blockDim.x + threadIdx.x;
    if (i < E) atomicAdd(&deg[dst[i]], 1);
}

__global__ void scan_block(const int* __restrict__ deg, int* __restrict__ incl,
                           int* __restrict__ bsum, int n) {
    __shared__ int sh[256];
    int tid = threadIdx.x;
    int i = blockIdx.x * 256 + tid;
    int v = (i < n) ? deg[i] : 0;
    sh[tid] = v;
    __syncthreads();
    #pragma unroll
    for (int off = 1; off < 256; off <<= 1) {
        int t = (tid >= off) ? sh[tid - off] : 0;
        __syncthreads();
        sh[tid] += t;
        __syncthreads();
    }
    if (i < n) incl[i] = sh[tid];
    if (tid == 255) bsum[blockIdx.x] = sh[255];
}

__global__ void scan_bsums(int* __restrict__ bsum, int nb) {
    __shared__ int sh[256];
    int tid = threadIdx.x;
    int v = (tid < nb) ? bsum[tid] : 0;
    sh[tid] = v;
    __syncthreads();
    #pragma unroll
    for (int off = 1; off < 256; off <<= 1) {
        int t = (tid >= off) ? sh[tid - off] : 0;
        __syncthreads();
        sh[tid] += t;
        __syncthreads();
    }
    if (tid < nb) bsum[tid] = sh[tid] - v;   // exclusive
}

__global__ void finalize_rowptr(const int* __restrict__ incl, const int* __restrict__ bsum,
                                int* __restrict__ rowptr, int n) {
    int i = blockIdx.x * blockDim.x + threadIdx.x;
    if (i < n) rowptr[i + 1] = incl[i] + bsum[i >> 8];
    if (i == 0) rowptr[0] = 0;
}

__global__ void scatter_edges(const int* __restrict__ src, const int* __restrict__ dst,
                              const int* __restrict__ rowptr, int* __restrict__ fill,
                              int* __restrict__ csrc, int E) {
    int i = blockIdx.x * blockDim.x + threadIdx.x;
    if (i >= E) return;
    int d = dst[i];
    int pos = rowptr[d] + atomicAdd(&fill[d], 1);
    csrc[pos] = src[i];
}

// ================= SGEMM: 128x64 (or 128x32) tile, 8xTN microtile =================
template<int BN, int TN>
__global__ void __launch_bounds__(256)
sgemm_t(const float* __restrict__ A, const float* __restrict__ B,
        float* __restrict__ C, int M, int K, int Nc) {
    constexpr int BM = 128, BK = 16, TM = 8;
    __shared__ float As[BK][BM];
    __shared__ float Bs[BK][BN];
    const int tid = threadIdx.x;
    const int tx = tid & 15;
    const int ty = tid >> 4;
    const int rowBase = blockIdx.y * BM;
    const int colBase = blockIdx.x * BN;

    float acc[TM][TN] = {};

    for (int k0 = 0; k0 < K; k0 += BK) {
        // A tile: 128x16 = 512 float4, 2 per thread (transposed into As)
        #pragma unroll
        for (int l = 0; l < 2; l++) {
            int i = tid + l * 256;
            int r = i >> 2, c4 = (i & 3) * 4;
            int gr = rowBase + r;
            float4 v = make_float4(0.f, 0.f, 0.f, 0.f);
            if (gr < M) v = *(const float4*)(A + (size_t)gr * K + k0 + c4);
            As[c4 + 0][r] = v.x; As[c4 + 1][r] = v.y;
            As[c4 + 2][r] = v.z; As[c4 + 3][r] = v.w;
        }
        // B tile
        if (BN == 64) {
            int kk = tid >> 4, n4 = (tid & 15) * 4;
            *(float4*)&Bs[kk][n4] = *(const float4*)(B + (size_t)(k0 + kk) * Nc + colBase + n4);
        } else {
            if (tid < 128) {
                int kk = tid >> 3, n4 = (tid & 7) * 4;
                *(float4*)&Bs[kk][n4] = *(const float4*)(B + (size_t)(k0 + kk) * Nc + colBase + n4);
            }
        }
        __syncthreads();
        #pragma unroll
        for (int kk = 0; kk < BK; kk++) {
            float av[TM], bv[TN];
            *(float4*)&av[0] = *(const float4*)&As[kk][ty * TM];
            *(float4*)&av[4] = *(const float4*)&As[kk][ty * TM + 4];
            if (TN == 4) {
                *(float4*)&bv[0] = *(const float4*)&Bs[kk][tx * TN];
            } else {
                bv[0] = Bs[kk][tx * TN]; bv[1] = Bs[kk][tx * TN + 1];
            }
            #pragma unroll
            for (int i = 0; i < TM; i++)
                #pragma unroll
                for (int j = 0; j < TN; j++)
                    acc[i][j] = fmaf(av[i], bv[j], acc[i][j]);
        }
        __syncthreads();
    }
    #pragma unroll
    for (int i = 0; i < TM; i++) {
        int r = rowBase + ty * TM + i;
        if (r >= M) continue;
        float* cp = C + (size_t)r * Nc + colBase + tx * TN;
        if (TN == 4) *(float4*)cp = *(float4*)&acc[i][0];
        else         *(float2*)cp = *(float2*)&acc[i][0];
    }
}

// dual small GEMM: blockIdx.z selects (B,C) pair; Nc=32, BN=32, TN=2
__global__ void __launch_bounds__(256)
sgemm_dual32(const float* __restrict__ A,
             const float* __restrict__ B1, float* __restrict__ C1,
             const float* __restrict__ B2, float* __restrict__ C2,
             int M, int K) {
    constexpr int BM = 128, BK = 16, TM = 8, BN = 32, TN = 2;
    const float* B = (blockIdx.x == 0) ? B1 : B2;
    float* C       = (blockIdx.x == 0) ? C1 : C2;
    __shared__ float As[BK][BM];
    __shared__ float Bs[BK][BN];
    const int tid = threadIdx.x;
    const int tx = tid & 15;
    const int ty = tid >> 4;
    const int rowBase = blockIdx.y * BM;

    float acc[TM][TN] = {};
    for (int k0 = 0; k0 < K; k0 += BK) {
        #pragma unroll
        for (int l = 0; l < 2; l++) {
            int i = tid + l * 256;
            int r = i >> 2, c4 = (i & 3) * 4;
            int gr = rowBase + r;
            float4 v = make_float4(0.f, 0.f, 0.f, 0.f);
            if (gr < M) v = *(const float4*)(A + (size_t)gr * K + k0 + c4);
            As[c4 + 0][r] = v.x; As[c4 + 1][r] = v.y;
            As[c4 + 2][r] = v.z; As[c4 + 3][r] = v.w;
        }
        if (tid < 128) {
            int kk = tid >> 3, n4 = (tid & 7) * 4;
            *(float4*)&Bs[kk][n4] = *(const float4*)(B + (size_t)(k0 + kk) * BN + n4);
        }
        __syncthreads();
        #pragma unroll
        for (int kk = 0; kk < BK; kk++) {
            float av[TM], bv[TN];
            *(float4*)&av[0] = *(const float4*)&As[kk][ty * TM];
            *(float4*)&av[4] = *(const float4*)&As[kk][ty * TM + 4];
            bv[0] = Bs[kk][tx * TN]; bv[1] = Bs[kk][tx * TN + 1];
            #pragma unroll
            for (int i = 0; i < TM; i++)
                #pragma unroll
                for (int j = 0; j < TN; j++)
                    acc[i][j] = fmaf(av[i], bv[j], acc[i][j]);
        }
        __syncthreads();
    }
    #pragma unroll
    for (int i = 0; i < TM; i++) {
        int r = rowBase + ty * TM + i;
        if (r >= M) continue;
        *(float2*)(C + (size_t)r * BN + tx * TN) = *(float2*)&acc[i][0];
    }
}

// ================= fused GATv2 edge layer (H=4, D=64), warp per node =================
// online softmax over in-edges via CSR; epilogue: /z, +res, elu.
__global__ void __launch_bounds__(256)
gat_layer_h4(const float* __restrict__ f, const int* __restrict__ rowptr,
             const int* __restrict__ csrc, const float* __restrict__ a,
             const float* __restrict__ res, float* __restrict__ out, int n) {
    int warp = (blockIdx.x * blockDim.x + threadIdx.x) >> 5;
    int lane = threadIdx.x & 31;
    if (warp >= n) return;
    const int node = warp;
    const int base = lane * 8;

    float ar[8], fd[8];
    {
        float4 t0 = __ldg((const float4*)(a + base));
        float4 t1 = __ldg((const float4*)(a + base + 4));
        ar[0]=t0.x; ar[1]=t0.y; ar[2]=t0.z; ar[3]=t0.w;
        ar[4]=t1.x; ar[5]=t1.y; ar[6]=t1.z; ar[7]=t1.w;
        const float4* fp = (const float4*)(f + (size_t)node * DIM + base);
        float4 d0 = fp[0], d1 = fp[1];
        fd[0]=d0.x; fd[1]=d0.y; fd[2]=d0.z; fd[3]=d0.w;
        fd[4]=d1.x; fd[5]=d1.y; fd[6]=d1.z; fd[7]=d1.w;
    }

    float acc[8] = {0,0,0,0,0,0,0,0};
    float m = NEGINF, s = 0.f;

    int e0 = rowptr[node], e1 = rowptr[node + 1];
    // prefetch first src feature
    float4 c0, c1v;
    {
        int sidx = csrc[e0];
        const float4* fp = (const float4*)(f + (size_t)sidx * DIM + base);
        c0 = fp[0]; c1v = fp[1];
    }
    for (int e = e0; e < e1; e++) {
        float u[8] = {c0.x, c0.y, c0.z, c0.w, c1v.x, c1v.y, c1v.z, c1v.w};
        if (e + 1 < e1) {
            int ns = csrc[e + 1];
            const float4* fp = (const float4*)(f + (size_t)ns * DIM + base);
            c0 = fp[0]; c1v = fp[1];
        }
        float p = 0.f;
        #pragma unroll
        for (int j = 0; j < 8; j++) {
            float v = u[j] + fd[j];
            float lv = v > 0.f ? v : 0.2f * v;
            p = fmaf(lv, ar[j], p);
        }
        p += __shfl_xor_sync(0xffffffffu, p, 1);
        p += __shfl_xor_sync(0xffffffffu, p, 2);
        p += __shfl_xor_sync(0xffffffffu, p, 4);

        float mn = fmaxf(m, p);
        float sc1 = __expf(m - mn);
        float sc2 = __expf(p - mn);
        s = s * sc1 + sc2;
        #pragma unroll
        for (int j = 0; j < 8; j++)
            acc[j] = fmaf(acc[j], sc1, sc2 * u[j]);
        m = mn;
    }
    float inv = 1.0f / s;
    float o[8];
    size_t oidx = (size_t)node * DIM + base;
    #pragma unroll
    for (int j = 0; j < 8; j++) o[j] = acc[j] * inv;
    if (res) {
        const float4* rp = (const float4*)(res + oidx);
        float4 r0 = rp[0], r1 = rp[1];
        o[0]+=r0.x; o[1]+=r0.y; o[2]+=r0.z; o[3]+=r0.w;
        o[4]+=r1.x; o[5]+=r1.y; o[6]+=r1.z; o[7]+=r1.w;
    }
    #pragma unroll
    for (int j = 0; j < 8; j++) o[j] = o[j] > 0.f ? o[j] : expm1f(o[j]);
    float4* op = (float4*)(out + oidx);
    op[0] = make_float4(o[0], o[1], o[2], o[3]);
    op[1] = make_float4(o[4], o[5], o[6], o[7]);
}

// ================= fused final layer (H=1, D=32), warp per node =================
__global__ void __launch_bounds__(256)
gat_layer_h1(const float* __restrict__ f2, const int* __restrict__ rowptr,
             const int* __restrict__ csrc, const float* __restrict__ a,
             const float* __restrict__ r2, float* __restrict__ out, int n) {
    int warp = (blockIdx.x * blockDim.x + threadIdx.x) >> 5;
    int lane = threadIdx.x & 31;
    if (warp >= n) return;
    const int node = warp;

    float ar = __ldg(a + lane);
    float fd = f2[(size_t)node * COUT + lane];

    float acc = 0.f, m = NEGINF, s = 0.f;
    int e0 = rowptr[node], e1 = rowptr[node + 1];
    float cur = f2[(size_t)csrc[e0] * COUT + lane];
    for (int e = e0; e < e1; e++) {
        float u = cur;
        if (e + 1 < e1) cur = f2[(size_t)csrc[e + 1] * COUT + lane];
        float v = u + fd;
        float lv = v > 0.f ? v : 0.2f * v;
        float p = lv * ar;
        p += __shfl_xor_sync(0xffffffffu, p, 1);
        p += __shfl_xor_sync(0xffffffffu, p, 2);
        p += __shfl_xor_sync(0xffffffffu, p, 4);
        p += __shfl_xor_sync(0xffffffffu, p, 8);
        p += __shfl_xor_sync(0xffffffffu, p, 16);
        float mn = fmaxf(m, p);
        float sc1 = __expf(m - mn);
        float sc2 = __expf(p - mn);
        s = s * sc1 + sc2;
        acc = fmaf(acc, sc1, sc2 * u);
        m = mn;
    }
    out[(size_t)node * COUT + lane] = acc / s + r2[(size_t)node * COUT + lane];
}

// ================= host =================
extern "C" void kernel_launch(void* const* d_in, const int* in_sizes, int n_in,
                              void* d_out, int out_size) {
    const float* x     = (const float*)d_in[0];
    const int*   src   = (const int*)  d_in[1];
    const int*   dst   = (const int*)  d_in[2];
    const float* W0    = (const float*)d_in[3];
    const float* a0    = (const float*)d_in[4];
    const float* W1    = (const float*)d_in[5];
    const float* a1    = (const float*)d_in[6];
    const float* W2    = (const float*)d_in[7];
    const float* a2    = (const float*)d_in[8];
    const float* Wres2 = (const float*)d_in[9];
    int E = in_sizes[1];
    if (E > EMAX) E = EMAX;

    float *f, *h0, *h1, *f2, *r2;
    int *deg, *fill, *tmp, *bsum, *rowptr, *csrc;
    cudaGetSymbolAddress((void**)&f,    g_f);
    cudaGetSymbolAddress((void**)&h0,   g_h0);
    cudaGetSymbolAddress((void**)&h1,   g_h1);
    cudaGetSymbolAddress((void**)&f2,   g_f2);
    cudaGetSymbolAddress((void**)&r2,   g_r2);
    cudaGetSymbolAddress((void**)&deg,  g_deg);
    cudaGetSymbolAddress((void**)&fill, g_fill);
    cudaGetSymbolAddress((void**)&tmp,  g_tmp);
    cudaGetSymbolAddress((void**)&bsum, g_bsum);
    cudaGetSymbolAddress((void**)&rowptr, g_rowptr);
    cudaGetSymbolAddress((void**)&csrc, g_csrc);

    const int TPB = 256;
    const int NB = (NNODES + 255) / 256;           // 196 scan blocks
    const int EB = (E + TPB - 1) / TPB;
    const int nodeWarpBlocks = (NNODES * 32 + TPB - 1) / TPB;

    // ---- CSR build ----
    zero_ints<<<NB, TPB>>>(deg, fill, NNODES);
    hist_deg<<<EB, TPB>>>(dst, deg, E);
    scan_block<<<NB, TPB>>>(deg, tmp, bsum, NNODES);
    scan_bsums<<<1, TPB>>>(bsum, NB);
    finalize_rowptr<<<NB, TPB>>>(tmp, bsum, rowptr, NNODES);
    scatter_edges<<<EB, TPB>>>(src, dst, rowptr, fill, csrc, E);

    dim3 gemmGrid(DIM / 64, (NNODES + 127) / 128);

    // ---- layer 0 ----
    sgemm_t<64, 4><<<gemmGrid, TPB>>>(x, W0, f, NNODES, DIM, DIM);
    gat_layer_h4<<<nodeWarpBlocks, TPB>>>(f, rowptr, csrc, a0, nullptr, h0, NNODES);

    // ---- layer 1 ----
    sgemm_t<64, 4><<<gemmGrid, TPB>>>(h0, W1, f, NNODES, DIM, DIM);
    gat_layer_h4<<<nodeWarpBlocks, TPB>>>(f, rowptr, csrc, a1, h0, h1, NNODES);

    // ---- layer 2 ----
    dim3 dualGrid(2, (NNODES + 127) / 128);
    sgemm_dual32<<<dualGrid, TPB>>>(h1, W2, f2, Wres2, r2, NNODES, DIM);
    gat_layer_h1<<<nodeWarpBlocks, TPB>>>(f2, rowptr, csrc, a2, r2, (float*)d_out, NNODES);
}

// round 4
// speedup vs baseline: 3.6638x; 1.2574x over previous
#include <cuda_runtime.h>
#include <cuda_bf16.h>
#include <math.h>
#include <stdint.h>

#define NNODES 50000
#define MPAD   50048            // 391 * 128
#define EMAX   850048
#define DIM    256
#define COUT   32
#define NEGINF __int_as_float(0xff800000)

// ---------------- scratch (device globals; no allocation allowed) ----------------
__device__ __align__(128) float g_f  [NNODES * DIM];
__device__ __align__(128) float g_h0 [NNODES * DIM];
__device__ __align__(128) float g_h1 [NNODES * DIM];
__device__ __align__(128) float g_f2 [NNODES * COUT];
__device__ __align__(128) float g_r2 [NNODES * COUT];
__device__ __align__(128) __nv_bfloat16 g_ahi[(size_t)MPAD * DIM];
__device__ __align__(128) __nv_bfloat16 g_alo[(size_t)MPAD * DIM];
__device__ __align__(128) __nv_bfloat16 g_bhi[DIM * DIM];
__device__ __align__(128) __nv_bfloat16 g_blo[DIM * DIM];
__device__ __align__(128) int   g_deg [NNODES];
__device__ __align__(128) int   g_fill[NNODES];
__device__ __align__(128) int   g_tmp [NNODES];
__device__ __align__(128) int   g_bsum[256];
__device__ __align__(128) int   g_rowptr[NNODES + 1];
__device__ __align__(128) int   g_csrc[EMAX];

// ================= helpers =================
__device__ __forceinline__ uint32_t smem_u32(const void* p) {
    uint32_t a;
    asm("{ .reg .u64 t; cvta.to.shared.u64 t, %1; cvt.u32.u64 %0, t; }" : "=r"(a) : "l"(p));
    return a;
}
__device__ __forceinline__ uint32_t swz(uint32_t off) {
    return off ^ ((off >> 3) & 0x70);   // SW128 for 128B rows
}
#define CP_ASYNC16(dst, src) \
    asm volatile("cp.async.cg.shared.global [%0], [%1], 16;" :: "r"(dst), "l"(src) : "memory")
#define CP_COMMIT()  asm volatile("cp.async.commit_group;" ::: "memory")
#define CP_WAIT1()   asm volatile("cp.async.wait_group 1;" ::: "memory")

__device__ __forceinline__ void ldm_x4(uint32_t* r, uint32_t addr) {
    asm volatile("ldmatrix.sync.aligned.m8n8.x4.shared.b16 {%0,%1,%2,%3}, [%4];"
                 : "=r"(r[0]), "=r"(r[1]), "=r"(r[2]), "=r"(r[3]) : "r"(addr));
}
__device__ __forceinline__ void mma16816(float* d, const uint32_t* a, const uint32_t* b) {
    asm volatile("mma.sync.aligned.m16n8k16.row.col.f32.bf16.bf16.f32 "
                 "{%0,%1,%2,%3}, {%4,%5,%6,%7}, {%8,%9}, {%0,%1,%2,%3};"
                 : "+f"(d[0]), "+f"(d[1]), "+f"(d[2]), "+f"(d[3])
                 : "r"(a[0]), "r"(a[1]), "r"(a[2]), "r"(a[3]), "r"(b[0]), "r"(b[1]));
}

// ================= CSR build =================
__global__ void zero_ints(int* __restrict__ a, int* __restrict__ b, int n) {
    int i = blockIdx.x * blockDim.x + threadIdx.x;
    if (i < n) { a[i] = 0; b[i] = 0; }
}
__global__ void hist_deg(const int* __restrict__ dst, int* __restrict__ deg, int E) {
    int i = blockIdx.x * blockDim.x + threadIdx.x;
    if (i < E) atomicAdd(&deg[dst[i]], 1);
}
__global__ void scan_block(const int* __restrict__ deg, int* __restrict__ incl,
                           int* __restrict__ bsum, int n) {
    __shared__ int sh[256];
    int tid = threadIdx.x;
    int i = blockIdx.x * 256 + tid;
    int v = (i < n) ? deg[i] : 0;
    sh[tid] = v;
    __syncthreads();
    #pragma unroll
    for (int off = 1; off < 256; off <<= 1) {
        int t = (tid >= off) ? sh[tid - off] : 0;
        __syncthreads();
        sh[tid] += t;
        __syncthreads();
    }
    if (i < n) incl[i] = sh[tid];
    if (tid == 255) bsum[blockIdx.x] = sh[255];
}
__global__ void scan_bsums(int* __restrict__ bsum, int nb) {
    __shared__ int sh[256];
    int tid = threadIdx.x;
    int v = (tid < nb) ? bsum[tid] : 0;
    sh[tid] = v;
    __syncthreads();
    #pragma unroll
    for (int off = 1; off < 256; off <<= 1) {
        int t = (tid >= off) ? sh[tid - off] : 0;
        __syncthreads();
        sh[tid] += t;
        __syncthreads();
    }
    if (tid < nb) bsum[tid] = sh[tid] - v;
}
__global__ void finalize_rowptr(const int* __restrict__ incl, const int* __restrict__ bsum,
                                int* __restrict__ rowptr, int n) {
    int i = blockIdx.x * blockDim.x + threadIdx.x;
    if (i < n) rowptr[i + 1] = incl[i] + bsum[i >> 8];
    if (i == 0) rowptr[0] = 0;
}
__global__ void scatter_edges(const int* __restrict__ src, const int* __restrict__ dst,
                              const int* __restrict__ rowptr, int* __restrict__ fill,
                              int* __restrict__ csrc, int E) {
    int i = blockIdx.x * blockDim.x + threadIdx.x;
    if (i >= E) return;
    int d = dst[i];
    int pos = rowptr[d] + atomicAdd(&fill[d], 1);
    csrc[pos] = src[i];
}

// ================= fp32 -> bf16 hi/lo split =================
__global__ void split_rows(const float* __restrict__ src, __nv_bfloat16* __restrict__ hi,
                           __nv_bfloat16* __restrict__ lo, int nvalid) {
    int i = blockIdx.x * blockDim.x + threadIdx.x;
    if (i >= MPAD * DIM) return;
    float v = (i < nvalid) ? src[i] : 0.f;
    __nv_bfloat16 h = __float2bfloat16(v);
    hi[i] = h;
    lo[i] = __float2bfloat16(v - __bfloat162float(h));
}

// W[k][n] row-major (256x256) -> Bt[n][k]
__global__ void transpose_split(const float* __restrict__ W, __nv_bfloat16* __restrict__ bh,
                                __nv_bfloat16* __restrict__ bl) {
    int i = blockIdx.x * blockDim.x + threadIdx.x;   // 65536
    int k = i >> 8, n = i & 255;
    float v = W[k * 256 + n];
    __nv_bfloat16 h = __float2bfloat16(v);
    bh[n * 256 + k] = h;
    bl[n * 256 + k] = __float2bfloat16(v - __bfloat162float(h));
}

// combined layer2 weights: Bt[n][k], n<32 from W2, n>=32 from Wres2 (each 256x32)
__global__ void transpose_split2(const float* __restrict__ W2, const float* __restrict__ Wr,
                                 __nv_bfloat16* __restrict__ bh, __nv_bfloat16* __restrict__ bl) {
    int i = blockIdx.x * blockDim.x + threadIdx.x;   // 64*256
    if (i >= 64 * 256) return;
    int n = i >> 8, k = i & 255;
    float v = (n < 32) ? W2[k * 32 + n] : Wr[k * 32 + (n - 32)];
    __nv_bfloat16 h = __float2bfloat16(v);
    bh[n * 256 + k] = h;
    bl[n * 256 + k] = __float2bfloat16(v - __bfloat162float(h));
}

// ================= mma.sync bf16x3 GEMM =================
// C[M,*] = A[M,256] * Bt^T ; A/B given as bf16 hi/lo, Bt is [n][k] K-major.
// CTA tile 128 x BN, 8 warps (2m x 4n), warp tile 64 x (NT*8).
// smem stage: Ahl[128][64] bf16 (cols 0-31 hi, 32-63 lo), Bhl[BN][64] same. SW128 swizzle.
template<int BN, int NT, bool SPLITOUT>
__global__ void __launch_bounds__(256, 2)
gemm_mma(const __nv_bfloat16* __restrict__ Ahi, const __nv_bfloat16* __restrict__ Alo,
         const __nv_bfloat16* __restrict__ Bhi, const __nv_bfloat16* __restrict__ Blo,
         float* __restrict__ C, float* __restrict__ C2, int M)
{
    constexpr int ACH = 1024;            // A chunks (16B) per stage: 128*128B/16
    constexpr int BCH = BN * 8;
    constexpr int STAGE = 16384 + BN * 128;
    extern __shared__ char smem[];
    const uint32_t sbase = smem_u32(smem);
    const int tid  = threadIdx.x;
    const int wid  = tid >> 5;
    const int lane = tid & 31;
    const int rowBase = blockIdx.y * 128;
    const int colBase = blockIdx.x * BN;
    const int m0w = (wid & 1) * 64;
    const int n0w = (wid >> 1) * (NT * 8);

    float acc[4][NT][4];
    #pragma unroll
    for (int i = 0; i < 4; i++)
        #pragma unroll
        for (int j = 0; j < NT; j++)
            #pragma unroll
            for (int q = 0; q < 4; q++) acc[i][j][q] = 0.f;

    // ---- stage loader ----
    auto load_stage = [&](int s, int buf) {
        const int k0 = s * 32;
        const uint32_t ab = sbase + buf * STAGE;
        const uint32_t bb = ab + 16384;
        #pragma unroll
        for (int c = tid; c < ACH + BCH; c += 256) {
            if (c < ACH) {
                int row = c >> 3, sub = c & 7;
                const __nv_bfloat16* g = (sub < 4)
                    ? Ahi + ((size_t)(rowBase + row) << 8) + k0 + sub * 8
                    : Alo + ((size_t)(rowBase + row) << 8) + k0 + (sub - 4) * 8;
                CP_ASYNC16(ab + swz(row * 128 + sub * 16), g);
            } else {
                int bc = c - ACH;
                int row = bc >> 3, sub = bc & 7;
                const __nv_bfloat16* g = (sub < 4)
                    ? Bhi + ((size_t)(colBase + row) << 8) + k0 + sub * 8
                    : Blo + ((size_t)(colBase + row) << 8) + k0 + (sub - 4) * 8;
                CP_ASYNC16(bb + swz(row * 128 + sub * 16), g);
            }
        }
        CP_COMMIT();
    };

    load_stage(0, 0);
    load_stage(1, 1);

    const int aRow = (lane & 15);            // within m16 tile
    const int aColX = (lane >> 4) << 4;      // +16B for lanes 16..31
    const int bRowX = (lane & 7) + ((lane & 16) ? 8 : 0);
    const int bColX = (lane & 8) ? 16 : 0;

    #pragma unroll
    for (int s = 0; s < 8; s++) {
        CP_WAIT1();
        __syncthreads();
        const uint32_t ab = sbase + (s & 1) * STAGE;
        const uint32_t bb = ab + 16384;
        #pragma unroll
        for (int kk = 0; kk < 2; kk++) {
            const int ckh = kk * 32;        // hi bytes
            const int ckl = 64 + kk * 32;   // lo bytes
            uint32_t ar[4][4], bh[NT / 2][4], bl[NT / 2][4];
            #pragma unroll
            for (int mt = 0; mt < 4; mt++) {
                int row = m0w + mt * 16 + aRow;
                ldm_x4(ar[mt], ab + swz(row * 128 + ckh + aColX));
            }
            #pragma unroll
            for (int bt = 0; bt < NT / 2; bt++) {
                int row = n0w + bt * 16 + bRowX;
                ldm_x4(bh[bt], bb + swz(row * 128 + ckh + bColX));
                ldm_x4(bl[bt], bb + swz(row * 128 + ckl + bColX));
            }
            #pragma unroll
            for (int mt = 0; mt < 4; mt++)
                #pragma unroll
                for (int nt = 0; nt < NT; nt++) {
                    mma16816(acc[mt][nt], ar[mt], &bh[nt >> 1][(nt & 1) * 2]);
                    mma16816(acc[mt][nt], ar[mt], &bl[nt >> 1][(nt & 1) * 2]);
                }
            // reuse ar for A-lo
            #pragma unroll
            for (int mt = 0; mt < 4; mt++) {
                int row = m0w + mt * 16 + aRow;
                ldm_x4(ar[mt], ab + swz(row * 128 + ckl + aColX));
            }
            #pragma unroll
            for (int mt = 0; mt < 4; mt++)
                #pragma unroll
                for (int nt = 0; nt < NT; nt++)
                    mma16816(acc[mt][nt], ar[mt], &bh[nt >> 1][(nt & 1) * 2]);
        }
        __syncthreads();
        if (s + 2 < 8) load_stage(s + 2, s & 1);
    }

    // ---- epilogue ----
    const int g = lane >> 2, tg = lane & 3;
    #pragma unroll
    for (int mt = 0; mt < 4; mt++) {
        int row0 = rowBase + m0w + mt * 16 + g;
        #pragma unroll
        for (int nt = 0; nt < NT; nt++) {
            int col = n0w + nt * 8 + tg * 2;
            if (!SPLITOUT) {
                int gc = colBase + col;
                if (row0 < M)
                    *(float2*)(C + (size_t)row0 * DIM + gc) = make_float2(acc[mt][nt][0], acc[mt][nt][1]);
                if (row0 + 8 < M)
                    *(float2*)(C + (size_t)(row0 + 8) * DIM + gc) = make_float2(acc[mt][nt][2], acc[mt][nt][3]);
            } else {
                float* base0 = (col < 32) ? C : C2;
                int cc = (col < 32) ? col : col - 32;
                if (row0 < M)
                    *(float2*)(base0 + (size_t)row0 * COUT + cc) = make_float2(acc[mt][nt][0], acc[mt][nt][1]);
                if (row0 + 8 < M)
                    *(float2*)(base0 + (size_t)(row0 + 8) * COUT + cc) = make_float2(acc[mt][nt][2], acc[mt][nt][3]);
            }
        }
    }
}

// ================= fused GATv2 edge layer (H=4, D=64), warp per node =================
__global__ void __launch_bounds__(256)
gat_layer_h4(const float* __restrict__ f, const int* __restrict__ rowptr,
             const int* __restrict__ csrc, const float* __restrict__ a,
             const float* __restrict__ res, float* __restrict__ out, int n) {
    int warp = (blockIdx.x * blockDim.x + threadIdx.x) >> 5;
    int lane = threadIdx.x & 31;
    if (warp >= n) return;
    const int node = warp;
    const int base = lane * 8;

    float ar[8], fd[8];
    {
        float4 t0 = __ldg((const float4*)(a + base));
        float4 t1 = __ldg((const float4*)(a + base + 4));
        ar[0]=t0.x; ar[1]=t0.y; ar[2]=t0.z; ar[3]=t0.w;
        ar[4]=t1.x; ar[5]=t1.y; ar[6]=t1.z; ar[7]=t1.w;
        const float4* fp = (const float4*)(f + (size_t)node * DIM + base);
        float4 d0 = fp[0], d1 = fp[1];
        fd[0]=d0.x; fd[1]=d0.y; fd[2]=d0.z; fd[3]=d0.w;
        fd[4]=d1.x; fd[5]=d1.y; fd[6]=d1.z; fd[7]=d1.w;
    }

    float acc[8] = {0,0,0,0,0,0,0,0};
    float m = NEGINF, s = 0.f;

    int e0 = rowptr[node], e1 = rowptr[node + 1];
    float4 c0, c1v;
    {
        int sidx = csrc[e0];
        const float4* fp = (const float4*)(f + (size_t)sidx * DIM + base);
        c0 = fp[0]; c1v = fp[1];
    }
    for (int e = e0; e < e1; e++) {
        float u[8] = {c0.x, c0.y, c0.z, c0.w, c1v.x, c1v.y, c1v.z, c1v.w};
        if (e + 1 < e1) {
            int ns = csrc[e + 1];
            const float4* fp = (const float4*)(f + (size_t)ns * DIM + base);
            c0 = fp[0]; c1v = fp[1];
        }
        float p = 0.f;
        #pragma unroll
        for (int j = 0; j < 8; j++) {
            float v = u[j] + fd[j];
            float lv = v > 0.f ? v : 0.2f * v;
            p = fmaf(lv, ar[j], p);
        }
        p += __shfl_xor_sync(0xffffffffu, p, 1);
        p += __shfl_xor_sync(0xffffffffu, p, 2);
        p += __shfl_xor_sync(0xffffffffu, p, 4);

        float mn = fmaxf(m, p);
        float sc1 = __expf(m - mn);
        float sc2 = __expf(p - mn);
        s = s * sc1 + sc2;
        #pragma unroll
        for (int j = 0; j < 8; j++)
            acc[j] = fmaf(acc[j], sc1, sc2 * u[j]);
        m = mn;
    }
    float inv = 1.0f / s;
    float o[8];
    size_t oidx = (size_t)node * DIM + base;
    #pragma unroll
    for (int j = 0; j < 8; j++) o[j] = acc[j] * inv;
    if (res) {
        const float4* rp = (const float4*)(res + oidx);
        float4 r0 = rp[0], r1 = rp[1];
        o[0]+=r0.x; o[1]+=r0.y; o[2]+=r0.z; o[3]+=r0.w;
        o[4]+=r1.x; o[5]+=r1.y; o[6]+=r1.z; o[7]+=r1.w;
    }
    #pragma unroll
    for (int j = 0; j < 8; j++) o[j] = o[j] > 0.f ? o[j] : expm1f(o[j]);
    float4* op = (float4*)(out + oidx);
    op[0] = make_float4(o[0], o[1], o[2], o[3]);
    op[1] = make_float4(o[4], o[5], o[6], o[7]);
}

// ================= fused final layer (H=1, D=32), warp per node =================
__global__ void __launch_bounds__(256)
gat_layer_h1(const float* __restrict__ f2, const int* __restrict__ rowptr,
             const int* __restrict__ csrc, const float* __restrict__ a,
             const float* __restrict__ r2, float* __restrict__ out, int n) {
    int warp = (blockIdx.x * blockDim.x + threadIdx.x) >> 5;
    int lane = threadIdx.x & 31;
    if (warp >= n) return;
    const int node = warp;

    float ar = __ldg(a + lane);
    float fd = f2[(size_t)node * COUT + lane];

    float acc = 0.f, m = NEGINF, s = 0.f;
    int e0 = rowptr[node], e1 = rowptr[node + 1];
    float cur = f2[(size_t)csrc[e0] * COUT + lane];
    for (int e = e0; e < e1; e++) {
        float u = cur;
        if (e + 1 < e1) cur = f2[(size_t)csrc[e + 1] * COUT + lane];
        float v = u + fd;
        float lv = v > 0.f ? v : 0.2f * v;
        float p = lv * ar;
        p += __shfl_xor_sync(0xffffffffu, p, 1);
        p += __shfl_xor_sync(0xffffffffu, p, 2);
        p += __shfl_xor_sync(0xffffffffu, p, 4);
        p += __shfl_xor_sync(0xffffffffu, p, 8);
        p += __shfl_xor_sync(0xffffffffu, p, 16);
        float mn = fmaxf(m, p);
        float sc1 = __expf(m - mn);
        float sc2 = __expf(p - mn);
        s = s * sc1 + sc2;
        acc = fmaf(acc, sc1, sc2 * u);
        m = mn;
    }
    out[(size_t)node * COUT + lane] = acc / s + r2[(size_t)node * COUT + lane];
}

// ================= host =================
extern "C" void kernel_launch(void* const* d_in, const int* in_sizes, int n_in,
                              void* d_out, int out_size) {
    const float* x     = (const float*)d_in[0];
    const int*   src   = (const int*)  d_in[1];
    const int*   dst   = (const int*)  d_in[2];
    const float* W0    = (const float*)d_in[3];
    const float* a0    = (const float*)d_in[4];
    const float* W1    = (const float*)d_in[5];
    const float* a1    = (const float*)d_in[6];
    const float* W2    = (const float*)d_in[7];
    const float* a2    = (const float*)d_in[8];
    const float* Wres2 = (const float*)d_in[9];
    int E = in_sizes[1];
    if (E > EMAX) E = EMAX;

    float *f, *h0, *h1, *f2, *r2;
    __nv_bfloat16 *ahi, *alo, *bhi, *blo;
    int *deg, *fill, *tmp, *bsum, *rowptr, *csrc;
    cudaGetSymbolAddress((void**)&f,    g_f);
    cudaGetSymbolAddress((void**)&h0,   g_h0);
    cudaGetSymbolAddress((void**)&h1,   g_h1);
    cudaGetSymbolAddress((void**)&f2,   g_f2);
    cudaGetSymbolAddress((void**)&r2,   g_r2);
    cudaGetSymbolAddress((void**)&ahi,  g_ahi);
    cudaGetSymbolAddress((void**)&alo,  g_alo);
    cudaGetSymbolAddress((void**)&bhi,  g_bhi);
    cudaGetSymbolAddress((void**)&blo,  g_blo);
    cudaGetSymbolAddress((void**)&deg,  g_deg);
    cudaGetSymbolAddress((void**)&fill, g_fill);
    cudaGetSymbolAddress((void**)&tmp,  g_tmp);
    cudaGetSymbolAddress((void**)&bsum, g_bsum);
    cudaGetSymbolAddress((void**)&rowptr, g_rowptr);
    cudaGetSymbolAddress((void**)&csrc, g_csrc);

    const int SMEM_BIG   = 2 * (16384 + 128 * 128);  // 65536
    const int SMEM_SMALL = 2 * (16384 + 64 * 128);   // 49152
    static int smem_set = 0;
    if (!smem_set) {
        cudaFuncSetAttribute((const void*)gemm_mma<128, 4, false>,
                             cudaFuncAttributeMaxDynamicSharedMemorySize, SMEM_BIG);
        cudaFuncSetAttribute((const void*)gemm_mma<64, 2, true>,
                             cudaFuncAttributeMaxDynamicSharedMemorySize, SMEM_SMALL);
        smem_set = 1;
    }

    const int TPB = 256;
    const int NB = (NNODES + 255) / 256;
    const int EB = (E + TPB - 1) / TPB;
    const int nodeWarpBlocks = (NNODES * 32 + TPB - 1) / TPB;
    const int splitBlocks = (MPAD * DIM + TPB - 1) / TPB;
    dim3 gemmGrid(2, MPAD / 128);
    dim3 gemmGridS(1, MPAD / 128);

    // ---- CSR build ----
    zero_ints<<<NB, TPB>>>(deg, fill, NNODES);
    hist_deg<<<EB, TPB>>>(dst, deg, E);
    scan_block<<<NB, TPB>>>(deg, tmp, bsum, NNODES);
    scan_bsums<<<1, TPB>>>(bsum, NB);
    finalize_rowptr<<<NB, TPB>>>(tmp, bsum, rowptr, NNODES);
    scatter_edges<<<EB, TPB>>>(src, dst, rowptr, fill, csrc, E);

    // ---- layer 0 ----
    split_rows<<<splitBlocks, TPB>>>(x, ahi, alo, NNODES * DIM);
    transpose_split<<<256, TPB>>>(W0, bhi, blo);
    gemm_mma<128, 4, false><<<gemmGrid, TPB, SMEM_BIG>>>(ahi, alo, bhi, blo, f, nullptr, NNODES);
    gat_layer_h4<<<nodeWarpBlocks, TPB>>>(f, rowptr, csrc, a0, nullptr, h0, NNODES);

    // ---- layer 1 ----
    split_rows<<<splitBlocks, TPB>>>(h0, ahi, alo, NNODES * DIM);
    transpose_split<<<256, TPB>>>(W1, bhi, blo);
    gemm_mma<128, 4, false><<<gemmGrid, TPB, SMEM_BIG>>>(ahi, alo, bhi, blo, f, nullptr, NNODES);
    gat_layer_h4<<<nodeWarpBlocks, TPB>>>(f, rowptr, csrc, a1, h0, h1, NNODES);

    // ---- layer 2 ----
    split_rows<<<splitBlocks, TPB>>>(h1, ahi, alo, NNODES * DIM);
    transpose_split2<<<64, TPB>>>(W2, Wres2, bhi, blo);
    gemm_mma<64, 2, true><<<gemmGridS, TPB, SMEM_SMALL>>>(ahi, alo, bhi, blo, f2, r2, NNODES);
    gat_layer_h1<<<nodeWarpBlocks, TPB>>>(f2, rowptr, csrc, a2, r2, (float*)d_out, NNODES);
}

// round 7
// speedup vs baseline: 3.6645x; 1.0002x over previous
#include <cuda_runtime.h>
#include <cuda_bf16.h>
#include <math.h>
#include <stdint.h>

#define NNODES 50000
#define MPAD   50048            // 391 * 128
#define EMAX   850048
#define DIM    256
#define COUT   32
#define NEGINF __int_as_float(0xff800000)

// ---------------- scratch (device globals; no allocation allowed) ----------------
__device__ __align__(128) float g_f  [NNODES * DIM];
__device__ __align__(128) float g_h0 [NNODES * DIM];
__device__ __align__(128) float g_h1 [NNODES * DIM];
__device__ __align__(128) float g_f2 [NNODES * COUT];
__device__ __align__(128) float g_r2 [NNODES * COUT];
__device__ __align__(128) __nv_bfloat16 g_ahi[(size_t)MPAD * DIM];
__device__ __align__(128) __nv_bfloat16 g_alo[(size_t)MPAD * DIM];
__device__ __align__(128) __nv_bfloat16 g_bhi[DIM * DIM];
__device__ __align__(128) __nv_bfloat16 g_blo[DIM * DIM];
__device__ __align__(128) int   g_deg [NNODES];
__device__ __align__(128) int   g_fill[NNODES];
__device__ __align__(128) int   g_tmp [NNODES];
__device__ __align__(128) int   g_bsum[256];
__device__ __align__(128) int   g_rowptr[NNODES + 1];
__device__ __align__(128) int   g_csrc[EMAX];

// ================= helpers =================
__device__ __forceinline__ uint32_t smem_u32(const void* p) {
    uint32_t a;
    asm("{ .reg .u64 t; cvta.to.shared.u64 t, %1; cvt.u32.u64 %0, t; }" : "=r"(a) : "l"(p));
    return a;
}
__device__ __forceinline__ uint32_t swz(uint32_t off) {
    return off ^ ((off >> 3) & 0x70);   // SW128 for 128B rows
}
#define CP_ASYNC16(dst, src) \
    asm volatile("cp.async.cg.shared.global [%0], [%1], 16;" :: "r"(dst), "l"(src) : "memory")
#define CP_COMMIT()  asm volatile("cp.async.commit_group;" ::: "memory")
#define CP_WAIT1()   asm volatile("cp.async.wait_group 1;" ::: "memory")

__device__ __forceinline__ void ldm_x4(uint32_t* r, uint32_t addr) {
    asm volatile("ldmatrix.sync.aligned.m8n8.x4.shared.b16 {%0,%1,%2,%3}, [%4];"
                 : "=r"(r[0]), "=r"(r[1]), "=r"(r[2]), "=r"(r[3]) : "r"(addr));
}
__device__ __forceinline__ void mma16816(float* d, const uint32_t* a, const uint32_t* b) {
    asm volatile("mma.sync.aligned.m16n8k16.row.col.f32.bf16.bf16.f32 "
                 "{%0,%1,%2,%3}, {%4,%5,%6,%7}, {%8,%9}, {%0,%1,%2,%3};"
                 : "+f"(d[0]), "+f"(d[1]), "+f"(d[2]), "+f"(d[3])
                 : "r"(a[0]), "r"(a[1]), "r"(a[2]), "r"(a[3]), "r"(b[0]), "r"(b[1]));
}

// ================= CSR build =================
__global__ void zero_ints(int* __restrict__ a, int* __restrict__ b, int n) {
    int i = blockIdx.x * blockDim.x + threadIdx.x;
    if (i < n) { a[i] = 0; b[i] = 0; }
}
__global__ void hist_deg(const int* __restrict__ dst, int* __restrict__ deg, int E) {
    int i = blockIdx.x * blockDim.x + threadIdx.x;
    if (i < E) atomicAdd(&deg[dst[i]], 1);
}
__global__ void scan_block(const int* __restrict__ deg, int* __restrict__ incl,
                           int* __restrict__ bsum, int n) {
    __shared__ int sh[256];
    int tid = threadIdx.x;
    int i = blockIdx.x * 256 + tid;
    int v = (i < n) ? deg[i] : 0;
    sh[tid] = v;
    __syncthreads();
    #pragma unroll
    for (int off = 1; off < 256; off <<= 1) {
        int t = (tid >= off) ? sh[tid - off] : 0;
        __syncthreads();
        sh[tid] += t;
        __syncthreads();
    }
    if (i < n) incl[i] = sh[tid];
    if (tid == 255) bsum[blockIdx.x] = sh[255];
}
__global__ void scan_bsums(int* __restrict__ bsum, int nb) {
    __shared__ int sh[256];
    int tid = threadIdx.x;
    int v = (tid < nb) ? bsum[tid] : 0;
    sh[tid] = v;
    __syncthreads();
    #pragma unroll
    for (int off = 1; off < 256; off <<= 1) {
        int t = (tid >= off) ? sh[tid - off] : 0;
        __syncthreads();
        sh[tid] += t;
        __syncthreads();
    }
    if (tid < nb) bsum[tid] = sh[tid] - v;
}
__global__ void finalize_rowptr(const int* __restrict__ incl, const int* __restrict__ bsum,
                                int* __restrict__ rowptr, int n) {
    int i = blockIdx.x * blockDim.x + threadIdx.x;
    if (i < n) rowptr[i + 1] = incl[i] + bsum[i >> 8];
    if (i == 0) rowptr[0] = 0;
}
__global__ void scatter_edges(const int* __restrict__ src, const int* __restrict__ dst,
                              const int* __restrict__ rowptr, int* __restrict__ fill,
                              int* __restrict__ csrc, int E) {
    int i = blockIdx.x * blockDim.x + threadIdx.x;
    if (i >= E) return;
    int d = dst[i];
    int pos = rowptr[d] + atomicAdd(&fill[d], 1);
    csrc[pos] = src[i];
}

// ================= fp32 -> bf16 hi/lo split =================
__global__ void split_rows(const float* __restrict__ src, __nv_bfloat16* __restrict__ hi,
                           __nv_bfloat16* __restrict__ lo, int nvalid) {
    int i = blockIdx.x * blockDim.x + threadIdx.x;
    if (i >= MPAD * DIM) return;
    float v = (i < nvalid) ? src[i] : 0.f;
    __nv_bfloat16 h = __float2bfloat16(v);
    hi[i] = h;
    lo[i] = __float2bfloat16(v - __bfloat162float(h));
}

// W[k][n] row-major (256x256) -> Bt[n][k]
__global__ void transpose_split(const float* __restrict__ W, __nv_bfloat16* __restrict__ bh,
                                __nv_bfloat16* __restrict__ bl) {
    int i = blockIdx.x * blockDim.x + threadIdx.x;   // 65536
    int k = i >> 8, n = i & 255;
    float v = W[k * 256 + n];
    __nv_bfloat16 h = __float2bfloat16(v);
    bh[n * 256 + k] = h;
    bl[n * 256 + k] = __float2bfloat16(v - __bfloat162float(h));
}

// combined layer2 weights: Bt[n][k], n<32 from W2, n>=32 from Wres2 (each 256x32)
__global__ void transpose_split2(const float* __restrict__ W2, const float* __restrict__ Wr,
                                 __nv_bfloat16* __restrict__ bh, __nv_bfloat16* __restrict__ bl) {
    int i = blockIdx.x * blockDim.x + threadIdx.x;   // 64*256
    if (i >= 64 * 256) return;
    int n = i >> 8, k = i & 255;
    float v = (n < 32) ? W2[k * 32 + n] : Wr[k * 32 + (n - 32)];
    __nv_bfloat16 h = __float2bfloat16(v);
    bh[n * 256 + k] = h;
    bl[n * 256 + k] = __float2bfloat16(v - __bfloat162float(h));
}

// ================= mma.sync bf16x3 GEMM =================
template<int BN, int NT, bool SPLITOUT>
__global__ void __launch_bounds__(256, 2)
gemm_mma(const __nv_bfloat16* __restrict__ Ahi, const __nv_bfloat16* __restrict__ Alo,
         const __nv_bfloat16* __restrict__ Bhi, const __nv_bfloat16* __restrict__ Blo,
         float* __restrict__ C, float* __restrict__ C2, int M)
{
    constexpr int ACH = 1024;
    constexpr int BCH = BN * 8;
    constexpr int STAGE = 16384 + BN * 128;
    extern __shared__ char smem[];
    const uint32_t sbase = smem_u32(smem);
    const int tid  = threadIdx.x;
    const int wid  = tid >> 5;
    const int lane = tid & 31;
    const int rowBase = blockIdx.y * 128;
    const int colBase = blockIdx.x * BN;
    const int m0w = (wid & 1) * 64;
    const int n0w = (wid >> 1) * (NT * 8);

    float acc[4][NT][4];
    #pragma unroll
    for (int i = 0; i < 4; i++)
        #pragma unroll
        for (int j = 0; j < NT; j++)
            #pragma unroll
            for (int q = 0; q < 4; q++) acc[i][j][q] = 0.f;

    auto load_stage = [&](int s, int buf) {
        const int k0 = s * 32;
        const uint32_t ab = sbase + buf * STAGE;
        const uint32_t bb = ab + 16384;
        #pragma unroll
        for (int c = tid; c < ACH + BCH; c += 256) {
            if (c < ACH) {
                int row = c >> 3, sub = c & 7;
                const __nv_bfloat16* g = (sub < 4)
                    ? Ahi + ((size_t)(rowBase + row) << 8) + k0 + sub * 8
                    : Alo + ((size_t)(rowBase + row) << 8) + k0 + (sub - 4) * 8;
                CP_ASYNC16(ab + swz(row * 128 + sub * 16), g);
            } else {
                int bc = c - ACH;
                int row = bc >> 3, sub = bc & 7;
                const __nv_bfloat16* g = (sub < 4)
                    ? Bhi + ((size_t)(colBase + row) << 8) + k0 + sub * 8
                    : Blo + ((size_t)(colBase + row) << 8) + k0 + (sub - 4) * 8;
                CP_ASYNC16(bb + swz(row * 128 + sub * 16), g);
            }
        }
        CP_COMMIT();
    };

    load_stage(0, 0);
    load_stage(1, 1);

    const int aRow = (lane & 15);
    const int aColX = (lane >> 4) << 4;
    const int bRowX = (lane & 7) + ((lane & 16) ? 8 : 0);
    const int bColX = (lane & 8) ? 16 : 0;

    #pragma unroll
    for (int s = 0; s < 8; s++) {
        CP_WAIT1();
        __syncthreads();
        const uint32_t ab = sbase + (s & 1) * STAGE;
        const uint32_t bb = ab + 16384;
        #pragma unroll
        for (int kk = 0; kk < 2; kk++) {
            const int ckh = kk * 32;
            const int ckl = 64 + kk * 32;
            uint32_t ar[4][4], bh[NT / 2][4], bl[NT / 2][4];
            #pragma unroll
            for (int mt = 0; mt < 4; mt++) {
                int row = m0w + mt * 16 + aRow;
                ldm_x4(ar[mt], ab + swz(row * 128 + ckh + aColX));
            }
            #pragma unroll
            for (int bt = 0; bt < NT / 2; bt++) {
                int row = n0w + bt * 16 + bRowX;
                ldm_x4(bh[bt], bb + swz(row * 128 + ckh + bColX));
                ldm_x4(bl[bt], bb + swz(row * 128 + ckl + bColX));
            }
            #pragma unroll
            for (int mt = 0; mt < 4; mt++)
                #pragma unroll
                for (int nt = 0; nt < NT; nt++) {
                    mma16816(acc[mt][nt], ar[mt], &bh[nt >> 1][(nt & 1) * 2]);
                    mma16816(acc[mt][nt], ar[mt], &bl[nt >> 1][(nt & 1) * 2]);
                }
            #pragma unroll
            for (int mt = 0; mt < 4; mt++) {
                int row = m0w + mt * 16 + aRow;
                ldm_x4(ar[mt], ab + swz(row * 128 + ckl + aColX));
            }
            #pragma unroll
            for (int mt = 0; mt < 4; mt++)
                #pragma unroll
                for (int nt = 0; nt < NT; nt++)
                    mma16816(acc[mt][nt], ar[mt], &bh[nt >> 1][(nt & 1) * 2]);
        }
        __syncthreads();
        if (s + 2 < 8) load_stage(s + 2, s & 1);
    }

    const int g = lane >> 2, tg = lane & 3;
    #pragma unroll
    for (int mt = 0; mt < 4; mt++) {
        int row0 = rowBase + m0w + mt * 16 + g;
        #pragma unroll
        for (int nt = 0; nt < NT; nt++) {
            int col = n0w + nt * 8 + tg * 2;
            if (!SPLITOUT) {
                int gc = colBase + col;
                if (row0 < M)
                    *(float2*)(C + (size_t)row0 * DIM + gc) = make_float2(acc[mt][nt][0], acc[mt][nt][1]);
                if (row0 + 8 < M)
                    *(float2*)(C + (size_t)(row0 + 8) * DIM + gc) = make_float2(acc[mt][nt][2], acc[mt][nt][3]);
            } else {
                float* base0 = (col < 32) ? C : C2;
                int cc = (col < 32) ? col : col - 32;
                if (row0 < M)
                    *(float2*)(base0 + (size_t)row0 * COUT + cc) = make_float2(acc[mt][nt][0], acc[mt][nt][1]);
                if (row0 + 8 < M)
                    *(float2*)(base0 + (size_t)(row0 + 8) * COUT + cc) = make_float2(acc[mt][nt][2], acc[mt][nt][3]);
            }
        }
    }
}

// ================= fused GATv2 edge layer (H=4, D=64), warp per node =================
// online softmax; epilogue: /z, [+res fp32], elu, fp32 out. Prefetch depth 2.
__global__ void __launch_bounds__(256)
gat_layer_h4(const float* __restrict__ f, const int* __restrict__ rowptr,
             const int* __restrict__ csrc, const float* __restrict__ a,
             const float* __restrict__ res, float* __restrict__ out, int n) {
    int warp = (blockIdx.x * blockDim.x + threadIdx.x) >> 5;
    int lane = threadIdx.x & 31;
    if (warp >= n) return;
    const int node = warp;
    const int base = lane * 8;

    float ar[8], fd[8];
    {
        float4 t0 = __ldg((const float4*)(a + base));
        float4 t1 = __ldg((const float4*)(a + base + 4));
        ar[0]=t0.x; ar[1]=t0.y; ar[2]=t0.z; ar[3]=t0.w;
        ar[4]=t1.x; ar[5]=t1.y; ar[6]=t1.z; ar[7]=t1.w;
        const float4* fp = (const float4*)(f + (size_t)node * DIM + base);
        float4 d0 = fp[0], d1 = fp[1];
        fd[0]=d0.x; fd[1]=d0.y; fd[2]=d0.z; fd[3]=d0.w;
        fd[4]=d1.x; fd[5]=d1.y; fd[6]=d1.z; fd[7]=d1.w;
    }

    float acc[8] = {0,0,0,0,0,0,0,0};
    float m = NEGINF, s = 0.f;

    int e0 = rowptr[node], e1 = rowptr[node + 1];
    // software pipeline depth 2
    float4 c0, c1v, p0, p1v;
    {
        int s0 = csrc[e0];
        const float4* fp = (const float4*)(f + (size_t)s0 * DIM + base);
        c0 = fp[0]; c1v = fp[1];
    }
    if (e0 + 1 < e1) {
        int s1 = csrc[e0 + 1];
        const float4* fp = (const float4*)(f + (size_t)s1 * DIM + base);
        p0 = fp[0]; p1v = fp[1];
    }
    for (int e = e0; e < e1; e++) {
        float u[8] = {c0.x, c0.y, c0.z, c0.w, c1v.x, c1v.y, c1v.z, c1v.w};
        c0 = p0; c1v = p1v;
        if (e + 2 < e1) {
            int ns = csrc[e + 2];
            const float4* fp = (const float4*)(f + (size_t)ns * DIM + base);
            p0 = fp[0]; p1v = fp[1];
        }
        float p = 0.f;
        #pragma unroll
        for (int j = 0; j < 8; j++) {
            float v = u[j] + fd[j];
            float lv = v > 0.f ? v : 0.2f * v;
            p = fmaf(lv, ar[j], p);
        }
        p += __shfl_xor_sync(0xffffffffu, p, 1);
        p += __shfl_xor_sync(0xffffffffu, p, 2);
        p += __shfl_xor_sync(0xffffffffu, p, 4);

        float mn = fmaxf(m, p);
        float sc1 = __expf(m - mn);
        float sc2 = __expf(p - mn);
        s = s * sc1 + sc2;
        #pragma unroll
        for (int j = 0; j < 8; j++)
            acc[j] = fmaf(acc[j], sc1, sc2 * u[j]);
        m = mn;
    }
    float inv = 1.0f / s;
    float o[8];
    size_t oidx = (size_t)node * DIM + base;
    #pragma unroll
    for (int j = 0; j < 8; j++) o[j] = acc[j] * inv;
    if (res) {
        const float4* rp = (const float4*)(res + oidx);
        float4 r0 = rp[0], r1 = rp[1];
        o[0]+=r0.x; o[1]+=r0.y; o[2]+=r0.z; o[3]+=r0.w;
        o[4]+=r1.x; o[5]+=r1.y; o[6]+=r1.z; o[7]+=r1.w;
    }
    #pragma unroll
    for (int j = 0; j < 8; j++) o[j] = o[j] > 0.f ? o[j] : expm1f(o[j]);
    float4* op = (float4*)(out + oidx);
    op[0] = make_float4(o[0], o[1], o[2], o[3]);
    op[1] = make_float4(o[4], o[5], o[6], o[7]);
}

// ================= fused final layer (H=1, D=32), warp per node =================
__global__ void __launch_bounds__(256)
gat_layer_h1(const float* __restrict__ f2, const int* __restrict__ rowptr,
             const int* __restrict__ csrc, const float* __restrict__ a,
             const float* __restrict__ r2, float* __restrict__ out, int n) {
    int warp = (blockIdx.x * blockDim.x + threadIdx.x) >> 5;
    int lane = threadIdx.x & 31;
    if (warp >= n) return;
    const int node = warp;

    float ar = __ldg(a + lane);
    float fd = f2[(size_t)node * COUT + lane];

    float acc = 0.f, m = NEGINF, s = 0.f;
    int e0 = rowptr[node], e1 = rowptr[node + 1];
    float cur = f2[(size_t)csrc[e0] * COUT + lane];
    float nxt = 0.f;
    if (e0 + 1 < e1) nxt = f2[(size_t)csrc[e0 + 1] * COUT + lane];
    for (int e = e0; e < e1; e++) {
        float u = cur;
        cur = nxt;
        if (e + 2 < e1) nxt = f2[(size_t)csrc[e + 2] * COUT + lane];
        float v = u + fd;
        float lv = v > 0.f ? v : 0.2f * v;
        float p = lv * ar;
        p += __shfl_xor_sync(0xffffffffu, p, 1);
        p += __shfl_xor_sync(0xffffffffu, p, 2);
        p += __shfl_xor_sync(0xffffffffu, p, 4);
        p += __shfl_xor_sync(0xffffffffu, p, 8);
        p += __shfl_xor_sync(0xffffffffu, p, 16);
        float mn = fmaxf(m, p);
        float sc1 = __expf(m - mn);
        float sc2 = __expf(p - mn);
        s = s * sc1 + sc2;
        acc = fmaf(acc, sc1, sc2 * u);
        m = mn;
    }
    out[(size_t)node * COUT + lane] = acc / s + r2[(size_t)node * COUT + lane];
}

// ================= host =================
extern "C" void kernel_launch(void* const* d_in, const int* in_sizes, int n_in,
                              void* d_out, int out_size) {
    const float* x     = (const float*)d_in[0];
    const int*   src   = (const int*)  d_in[1];
    const int*   dst   = (const int*)  d_in[2];
    const float* W0    = (const float*)d_in[3];
    const float* a0    = (const float*)d_in[4];
    const float* W1    = (const float*)d_in[5];
    const float* a1    = (const float*)d_in[6];
    const float* W2    = (const float*)d_in[7];
    const float* a2    = (const float*)d_in[8];
    const float* Wres2 = (const float*)d_in[9];
    int E = in_sizes[1];
    if (E > EMAX) E = EMAX;

    float *f, *h0, *h1, *f2, *r2;
    __nv_bfloat16 *ahi, *alo, *bhi, *blo;
    int *deg, *fill, *tmp, *bsum, *rowptr, *csrc;
    cudaGetSymbolAddress((void**)&f,    g_f);
    cudaGetSymbolAddress((void**)&h0,   g_h0);
    cudaGetSymbolAddress((void**)&h1,   g_h1);
    cudaGetSymbolAddress((void**)&f2,   g_f2);
    cudaGetSymbolAddress((void**)&r2,   g_r2);
    cudaGetSymbolAddress((void**)&ahi,  g_ahi);
    cudaGetSymbolAddress((void**)&alo,  g_alo);
    cudaGetSymbolAddress((void**)&bhi,  g_bhi);
    cudaGetSymbolAddress((void**)&blo,  g_blo);
    cudaGetSymbolAddress((void**)&deg,  g_deg);
    cudaGetSymbolAddress((void**)&fill, g_fill);
    cudaGetSymbolAddress((void**)&tmp,  g_tmp);
    cudaGetSymbolAddress((void**)&bsum, g_bsum);
    cudaGetSymbolAddress((void**)&rowptr, g_rowptr);
    cudaGetSymbolAddress((void**)&csrc, g_csrc);

    const int SMEM_BIG   = 2 * (16384 + 128 * 128);  // 65536
    const int SMEM_SMALL = 2 * (16384 + 64 * 128);   // 49152
    static int smem_set = 0;
    if (!smem_set) {
        cudaFuncSetAttribute((const void*)gemm_mma<128, 4, false>,
                             cudaFuncAttributeMaxDynamicSharedMemorySize, SMEM_BIG);
        cudaFuncSetAttribute((const void*)gemm_mma<64, 2, true>,
                             cudaFuncAttributeMaxDynamicSharedMemorySize, SMEM_SMALL);
        smem_set = 1;
    }

    const int TPB = 256;
    const int NB = (NNODES + 255) / 256;
    const int EB = (E + TPB - 1) / TPB;
    const int nodeWarpBlocks = (NNODES * 32 + TPB - 1) / TPB;
    const int splitBlocks = (MPAD * DIM + TPB - 1) / TPB;
    dim3 gemmGrid(2, MPAD / 128);
    dim3 gemmGridS(1, MPAD / 128);

    // ---- layer-0 projection first: the big GEMM is launch #4 (ncu captures #4) ----
    split_rows<<<splitBlocks, TPB>>>(x, ahi, alo, NNODES * DIM);               // 1
    transpose_split<<<256, TPB>>>(W0, bhi, blo);                               // 2
    zero_ints<<<NB, TPB>>>(deg, fill, NNODES);                                 // 3
    gemm_mma<128, 4, false><<<gemmGrid, TPB, SMEM_BIG>>>(ahi, alo, bhi, blo, f, nullptr, NNODES); // 4

    // ---- CSR build ----
    hist_deg<<<EB, TPB>>>(dst, deg, E);
    scan_block<<<NB, TPB>>>(deg, tmp, bsum, NNODES);
    scan_bsums<<<1, TPB>>>(bsum, NB);
    finalize_rowptr<<<NB, TPB>>>(tmp, bsum, rowptr, NNODES);
    scatter_edges<<<EB, TPB>>>(src, dst, rowptr, fill, csrc, E);

    // ---- layer 0 edge phase ----
    gat_layer_h4<<<nodeWarpBlocks, TPB>>>(f, rowptr, csrc, a0, nullptr, h0, NNODES);

    // ---- layer 1 ----
    split_rows<<<splitBlocks, TPB>>>(h0, ahi, alo, NNODES * DIM);
    transpose_split<<<256, TPB>>>(W1, bhi, blo);
    gemm_mma<128, 4, false><<<gemmGrid, TPB, SMEM_BIG>>>(ahi, alo, bhi, blo, f, nullptr, NNODES);
    gat_layer_h4<<<nodeWarpBlocks, TPB>>>(f, rowptr, csrc, a1, h0, h1, NNODES);

    // ---- layer 2 ----
    split_rows<<<splitBlocks, TPB>>>(h1, ahi, alo, NNODES * DIM);
    transpose_split2<<<64, TPB>>>(W2, Wres2, bhi, blo);
    gemm_mma<64, 2, true><<<gemmGridS, TPB, SMEM_SMALL>>>(ahi, alo, bhi, blo, f2, r2, NNODES);
    gat_layer_h1<<<nodeWarpBlocks, TPB>>>(f2, rowptr, csrc, a2, r2, (float*)d_out, NNODES);
}

// round 8
// speedup vs baseline: 3.6927x; 1.0077x over previous
#include <cuda_runtime.h>
#include <cuda_bf16.h>
#include <math.h>
#include <stdint.h>

#define NNODES 50000
#define MPAD   50048            // 391 * 128
#define EMAX   850048
#define DIM    256
#define COUT   32
#define NEGINF __int_as_float(0xff800000)

// ---------------- scratch (device globals; no allocation allowed) ----------------
__device__ __align__(128) float g_f  [NNODES * DIM];
__device__ __align__(128) float g_h0 [NNODES * DIM];
__device__ __align__(128) float g_h1 [NNODES * DIM];
__device__ __align__(128) float g_f2 [NNODES * COUT];
__device__ __align__(128) float g_r2 [NNODES * COUT];
__device__ __align__(128) __nv_bfloat16 g_ahi[(size_t)MPAD * DIM];
__device__ __align__(128) __nv_bfloat16 g_alo[(size_t)MPAD * DIM];
__device__ __align__(128) __nv_bfloat16 g_bh0[DIM * DIM];
__device__ __align__(128) __nv_bfloat16 g_bl0[DIM * DIM];
__device__ __align__(128) __nv_bfloat16 g_bh1[DIM * DIM];
__device__ __align__(128) __nv_bfloat16 g_bl1[DIM * DIM];
__device__ __align__(128) __nv_bfloat16 g_bh2[64 * DIM];
__device__ __align__(128) __nv_bfloat16 g_bl2[64 * DIM];
__device__ __align__(128) int   g_deg [NNODES];
__device__ __align__(128) int   g_fill[NNODES];
__device__ __align__(128) int   g_tmp [NNODES];
__device__ __align__(128) int   g_bsum[256];
__device__ __align__(128) int   g_rowptr[NNODES + 1];
__device__ __align__(128) int   g_csrc[EMAX];

// ================= helpers =================
__device__ __forceinline__ uint32_t smem_u32(const void* p) {
    uint32_t a;
    asm("{ .reg .u64 t; cvta.to.shared.u64 t, %1; cvt.u32.u64 %0, t; }" : "=r"(a) : "l"(p));
    return a;
}
__device__ __forceinline__ uint32_t swz(uint32_t off) {
    return off ^ ((off >> 3) & 0x70);   // SW128 for 128B rows
}
#define CP_ASYNC16(dst, src) \
    asm volatile("cp.async.cg.shared.global [%0], [%1], 16;" :: "r"(dst), "l"(src) : "memory")
#define CP_COMMIT()  asm volatile("cp.async.commit_group;" ::: "memory")

__device__ __forceinline__ void ldm_x4(uint32_t* r, uint32_t addr) {
    asm volatile("ldmatrix.sync.aligned.m8n8.x4.shared.b16 {%0,%1,%2,%3}, [%4];"
                 : "=r"(r[0]), "=r"(r[1]), "=r"(r[2]), "=r"(r[3]) : "r"(addr));
}
__device__ __forceinline__ void mma16816(float* d, const uint32_t* a, const uint32_t* b) {
    asm volatile("mma.sync.aligned.m16n8k16.row.col.f32.bf16.bf16.f32 "
                 "{%0,%1,%2,%3}, {%4,%5,%6,%7}, {%8,%9}, {%0,%1,%2,%3};"
                 : "+f"(d[0]), "+f"(d[1]), "+f"(d[2]), "+f"(d[3])
                 : "r"(a[0]), "r"(a[1]), "r"(a[2]), "r"(a[3]), "r"(b[0]), "r"(b[1]));
}

// ================= CSR build =================
__global__ void zero_ints(int* __restrict__ a, int* __restrict__ b, int n) {
    int i = blockIdx.x * blockDim.x + threadIdx.x;
    if (i < n) { a[i] = 0; b[i] = 0; }
}
__global__ void hist_deg(const int* __restrict__ dst, int* __restrict__ deg, int E) {
    int i = blockIdx.x * blockDim.x + threadIdx.x;
    if (i < E) atomicAdd(&deg[dst[i]], 1);
}
__global__ void scan_block(const int* __restrict__ deg, int* __restrict__ incl,
                           int* __restrict__ bsum, int n) {
    __shared__ int sh[256];
    int tid = threadIdx.x;
    int i = blockIdx.x * 256 + tid;
    int v = (i < n) ? deg[i] : 0;
    sh[tid] = v;
    __syncthreads();
    #pragma unroll
    for (int off = 1; off < 256; off <<= 1) {
        int t = (tid >= off) ? sh[tid - off] : 0;
        __syncthreads();
        sh[tid] += t;
        __syncthreads();
    }
    if (i < n) incl[i] = sh[tid];
    if (tid == 255) bsum[blockIdx.x] = sh[255];
}
// merged: scan of block sums (in smem, redone per block) + rowptr finalize
__global__ void finalize_rowptr(const int* __restrict__ incl, const int* __restrict__ bsum,
                                int* __restrict__ rowptr, int n, int nb) {
    __shared__ int sb[256];
    int tid = threadIdx.x;
    int v = (tid < nb) ? bsum[tid] : 0;
    sb[tid] = v;
    __syncthreads();
    #pragma unroll
    for (int off = 1; off < 256; off <<= 1) {
        int t = (tid >= off) ? sb[tid - off] : 0;
        __syncthreads();
        sb[tid] += t;
        __syncthreads();
    }
    int excl = sb[tid] - v;
    __syncthreads();
    sb[tid] = excl;
    __syncthreads();
    int i = blockIdx.x * blockDim.x + tid;
    if (i < n) rowptr[i + 1] = incl[i] + sb[blockIdx.x];
    if (i == 0) rowptr[0] = 0;
}
__global__ void scatter_edges(const int* __restrict__ src, const int* __restrict__ dst,
                              const int* __restrict__ rowptr, int* __restrict__ fill,
                              int* __restrict__ csrc, int E) {
    int i = blockIdx.x * blockDim.x + threadIdx.x;
    if (i >= E) return;
    int d = dst[i];
    int pos = rowptr[d] + atomicAdd(&fill[d], 1);
    csrc[pos] = src[i];
}

// ================= fp32 -> bf16 hi/lo split =================
__global__ void split_rows(const float* __restrict__ src, __nv_bfloat16* __restrict__ hi,
                           __nv_bfloat16* __restrict__ lo, int nvalid) {
    int i = blockIdx.x * blockDim.x + threadIdx.x;
    if (i >= MPAD * DIM) return;
    float v = (i < nvalid) ? src[i] : 0.f;
    __nv_bfloat16 h = __float2bfloat16(v);
    hi[i] = h;
    lo[i] = __float2bfloat16(v - __bfloat162float(h));
}

// all three layers' weight transposes + splits in one kernel
__global__ void transpose_all(const float* __restrict__ W0, const float* __restrict__ W1,
                              const float* __restrict__ W2, const float* __restrict__ Wr,
                              __nv_bfloat16* __restrict__ bh0, __nv_bfloat16* __restrict__ bl0,
                              __nv_bfloat16* __restrict__ bh1, __nv_bfloat16* __restrict__ bl1,
                              __nv_bfloat16* __restrict__ bh2, __nv_bfloat16* __restrict__ bl2) {
    int i = blockIdx.x * blockDim.x + threadIdx.x;
    if (i < 65536) {
        int k = i >> 8, n = i & 255;
        float v = W0[k * 256 + n];
        __nv_bfloat16 h = __float2bfloat16(v);
        bh0[n * 256 + k] = h;
        bl0[n * 256 + k] = __float2bfloat16(v - __bfloat162float(h));
    } else if (i < 131072) {
        int j = i - 65536;
        int k = j >> 8, n = j & 255;
        float v = W1[k * 256 + n];
        __nv_bfloat16 h = __float2bfloat16(v);
        bh1[n * 256 + k] = h;
        bl1[n * 256 + k] = __float2bfloat16(v - __bfloat162float(h));
    } else if (i < 147456) {
        int j = i - 131072;
        int n = j >> 8, k = j & 255;
        float v = (n < 32) ? W2[k * 32 + n] : Wr[k * 32 + (n - 32)];
        __nv_bfloat16 h = __float2bfloat16(v);
        bh2[n * 256 + k] = h;
        bl2[n * 256 + k] = __float2bfloat16(v - __bfloat162float(h));
    }
}

// ================= mma.sync bf16x3 GEMM — 3-stage cp.async pipeline =================
template<int BN, int NT, bool SPLITOUT>
__global__ void __launch_bounds__(256, 2)
gemm_mma(const __nv_bfloat16* __restrict__ Ahi, const __nv_bfloat16* __restrict__ Alo,
         const __nv_bfloat16* __restrict__ Bhi, const __nv_bfloat16* __restrict__ Blo,
         float* __restrict__ C, float* __restrict__ C2, int M)
{
    constexpr int ACH = 1024;
    constexpr int BCH = BN * 8;
    constexpr int STAGE = 16384 + BN * 128;
    extern __shared__ char smem[];
    const uint32_t sbase = smem_u32(smem);
    const int tid  = threadIdx.x;
    const int wid  = tid >> 5;
    const int lane = tid & 31;
    const int rowBase = blockIdx.y * 128;
    const int colBase = blockIdx.x * BN;
    const int m0w = (wid & 1) * 64;
    const int n0w = (wid >> 1) * (NT * 8);

    float acc[4][NT][4];
    #pragma unroll
    for (int i = 0; i < 4; i++)
        #pragma unroll
        for (int j = 0; j < NT; j++)
            #pragma unroll
            for (int q = 0; q < 4; q++) acc[i][j][q] = 0.f;

    auto load_stage = [&](int s, int buf) {
        const int k0 = s * 32;
        const uint32_t ab = sbase + buf * STAGE;
        const uint32_t bb = ab + 16384;
        #pragma unroll
        for (int c = tid; c < ACH + BCH; c += 256) {
            if (c < ACH) {
                int row = c >> 3, sub = c & 7;
                const __nv_bfloat16* g = (sub < 4)
                    ? Ahi + ((size_t)(rowBase + row) << 8) + k0 + sub * 8
                    : Alo + ((size_t)(rowBase + row) << 8) + k0 + (sub - 4) * 8;
                CP_ASYNC16(ab + swz(row * 128 + sub * 16), g);
            } else {
                int bc = c - ACH;
                int row = bc >> 3, sub = bc & 7;
                const __nv_bfloat16* g = (sub < 4)
                    ? Bhi + ((size_t)(colBase + row) << 8) + k0 + sub * 8
                    : Blo + ((size_t)(colBase + row) << 8) + k0 + (sub - 4) * 8;
                CP_ASYNC16(bb + swz(row * 128 + sub * 16), g);
            }
        }
        CP_COMMIT();
    };

    load_stage(0, 0);
    load_stage(1, 1);
    load_stage(2, 2);

    const int aRow = (lane & 15);
    const int aColX = (lane >> 4) << 4;
    const int bRowX = (lane & 7) + ((lane & 16) ? 8 : 0);
    const int bColX = (lane & 8) ? 16 : 0;

    #pragma unroll
    for (int s = 0; s < 8; s++) {
        // exact tail waits: guarantee stage s has landed
        if (s <= 5)      asm volatile("cp.async.wait_group 2;" ::: "memory");
        else if (s == 6) asm volatile("cp.async.wait_group 1;" ::: "memory");
        else             asm volatile("cp.async.wait_group 0;" ::: "memory");
        __syncthreads();
        const uint32_t ab = sbase + (s % 3) * STAGE;
        const uint32_t bb = ab + 16384;
        #pragma unroll
        for (int kk = 0; kk < 2; kk++) {
            const int ckh = kk * 32;
            const int ckl = 64 + kk * 32;
            uint32_t ar[4][4], bh[NT / 2][4], bl[NT / 2][4];
            #pragma unroll
            for (int mt = 0; mt < 4; mt++) {
                int row = m0w + mt * 16 + aRow;
                ldm_x4(ar[mt], ab + swz(row * 128 + ckh + aColX));
            }
            #pragma unroll
            for (int bt = 0; bt < NT / 2; bt++) {
                int row = n0w + bt * 16 + bRowX;
                ldm_x4(bh[bt], bb + swz(row * 128 + ckh + bColX));
                ldm_x4(bl[bt], bb + swz(row * 128 + ckl + bColX));
            }
            #pragma unroll
            for (int mt = 0; mt < 4; mt++)
                #pragma unroll
                for (int nt = 0; nt < NT; nt++) {
                    mma16816(acc[mt][nt], ar[mt], &bh[nt >> 1][(nt & 1) * 2]);
                    mma16816(acc[mt][nt], ar[mt], &bl[nt >> 1][(nt & 1) * 2]);
                }
            #pragma unroll
            for (int mt = 0; mt < 4; mt++) {
                int row = m0w + mt * 16 + aRow;
                ldm_x4(ar[mt], ab + swz(row * 128 + ckl + aColX));
            }
            #pragma unroll
            for (int mt = 0; mt < 4; mt++)
                #pragma unroll
                for (int nt = 0; nt < NT; nt++)
                    mma16816(acc[mt][nt], ar[mt], &bh[nt >> 1][(nt & 1) * 2]);
        }
        __syncthreads();
        if (s + 3 < 8) load_stage(s + 3, s % 3);
    }

    const int g = lane >> 2, tg = lane & 3;
    #pragma unroll
    for (int mt = 0; mt < 4; mt++) {
        int row0 = rowBase + m0w + mt * 16 + g;
        #pragma unroll
        for (int nt = 0; nt < NT; nt++) {
            int col = n0w + nt * 8 + tg * 2;
            if (!SPLITOUT) {
                int gc = colBase + col;
                if (row0 < M)
                    *(float2*)(C + (size_t)row0 * DIM + gc) = make_float2(acc[mt][nt][0], acc[mt][nt][1]);
                if (row0 + 8 < M)
                    *(float2*)(C + (size_t)(row0 + 8) * DIM + gc) = make_float2(acc[mt][nt][2], acc[mt][nt][3]);
            } else {
                float* base0 = (col < 32) ? C : C2;
                int cc = (col < 32) ? col : col - 32;
                if (row0 < M)
                    *(float2*)(base0 + (size_t)row0 * COUT + cc) = make_float2(acc[mt][nt][0], acc[mt][nt][1]);
                if (row0 + 8 < M)
                    *(float2*)(base0 + (size_t)(row0 + 8) * COUT + cc) = make_float2(acc[mt][nt][2], acc[mt][nt][3]);
            }
        }
    }
}

// ================= fused GATv2 edge layer (H=4, D=64), warp per node =================
__global__ void __launch_bounds__(256)
gat_layer_h4(const float* __restrict__ f, const int* __restrict__ rowptr,
             const int* __restrict__ csrc, const float* __restrict__ a,
             const float* __restrict__ res, float* __restrict__ out, int n) {
    int warp = (blockIdx.x * blockDim.x + threadIdx.x) >> 5;
    int lane = threadIdx.x & 31;
    if (warp >= n) return;
    const int node = warp;
    const int base = lane * 8;

    float ar[8], fd[8];
    {
        float4 t0 = __ldg((const float4*)(a + base));
        float4 t1 = __ldg((const float4*)(a + base + 4));
        ar[0]=t0.x; ar[1]=t0.y; ar[2]=t0.z; ar[3]=t0.w;
        ar[4]=t1.x; ar[5]=t1.y; ar[6]=t1.z; ar[7]=t1.w;
        const float4* fp = (const float4*)(f + (size_t)node * DIM + base);
        float4 d0 = fp[0], d1 = fp[1];
        fd[0]=d0.x; fd[1]=d0.y; fd[2]=d0.z; fd[3]=d0.w;
        fd[4]=d1.x; fd[5]=d1.y; fd[6]=d1.z; fd[7]=d1.w;
    }

    float acc[8] = {0,0,0,0,0,0,0,0};
    float m = NEGINF, s = 0.f;

    int e0 = rowptr[node], e1 = rowptr[node + 1];
    float4 c0, c1v, p0, p1v;
    {
        int s0 = csrc[e0];
        const float4* fp = (const float4*)(f + (size_t)s0 * DIM + base);
        c0 = fp[0]; c1v = fp[1];
    }
    if (e0 + 1 < e1) {
        int s1 = csrc[e0 + 1];
        const float4* fp = (const float4*)(f + (size_t)s1 * DIM + base);
        p0 = fp[0]; p1v = fp[1];
    }
    for (int e = e0; e < e1; e++) {
        float u[8] = {c0.x, c0.y, c0.z, c0.w, c1v.x, c1v.y, c1v.z, c1v.w};
        c0 = p0; c1v = p1v;
        if (e + 2 < e1) {
            int ns = csrc[e + 2];
            const float4* fp = (const float4*)(f + (size_t)ns * DIM + base);
            p0 = fp[0]; p1v = fp[1];
        }
        float p = 0.f;
        #pragma unroll
        for (int j = 0; j < 8; j++) {
            float v = u[j] + fd[j];
            float lv = v > 0.f ? v : 0.2f * v;
            p = fmaf(lv, ar[j], p);
        }
        p += __shfl_xor_sync(0xffffffffu, p, 1);
        p += __shfl_xor_sync(0xffffffffu, p, 2);
        p += __shfl_xor_sync(0xffffffffu, p, 4);

        float mn = fmaxf(m, p);
        float sc1 = __expf(m - mn);
        float sc2 = __expf(p - mn);
        s = s * sc1 + sc2;
        #pragma unroll
        for (int j = 0; j < 8; j++)
            acc[j] = fmaf(acc[j], sc1, sc2 * u[j]);
        m = mn;
    }
    float inv = 1.0f / s;
    float o[8];
    size_t oidx = (size_t)node * DIM + base;
    #pragma unroll
    for (int j = 0; j < 8; j++) o[j] = acc[j] * inv;
    if (res) {
        const float4* rp = (const float4*)(res + oidx);
        float4 r0 = rp[0], r1 = rp[1];
        o[0]+=r0.x; o[1]+=r0.y; o[2]+=r0.z; o[3]+=r0.w;
        o[4]+=r1.x; o[5]+=r1.y; o[6]+=r1.z; o[7]+=r1.w;
    }
    #pragma unroll
    for (int j = 0; j < 8; j++) o[j] = o[j] > 0.f ? o[j] : expm1f(o[j]);
    float4* op = (float4*)(out + oidx);
    op[0] = make_float4(o[0], o[1], o[2], o[3]);
    op[1] = make_float4(o[4], o[5], o[6], o[7]);
}

// ================= fused final layer (H=1, D=32), warp per node =================
__global__ void __launch_bounds__(256)
gat_layer_h1(const float* __restrict__ f2, const int* __restrict__ rowptr,
             const int* __restrict__ csrc, const float* __restrict__ a,
             const float* __restrict__ r2, float* __restrict__ out, int n) {
    int warp = (blockIdx.x * blockDim.x + threadIdx.x) >> 5;
    int lane = threadIdx.x & 31;
    if (warp >= n) return;
    const int node = warp;

    float ar = __ldg(a + lane);
    float fd = f2[(size_t)node * COUT + lane];

    float acc = 0.f, m = NEGINF, s = 0.f;
    int e0 = rowptr[node], e1 = rowptr[node + 1];
    float cur = f2[(size_t)csrc[e0] * COUT + lane];
    float nxt = 0.f;
    if (e0 + 1 < e1) nxt = f2[(size_t)csrc[e0 + 1] * COUT + lane];
    for (int e = e0; e < e1; e++) {
        float u = cur;
        cur = nxt;
        if (e + 2 < e1) nxt = f2[(size_t)csrc[e + 2] * COUT + lane];
        float v = u + fd;
        float lv = v > 0.f ? v : 0.2f * v;
        float p = lv * ar;
        p += __shfl_xor_sync(0xffffffffu, p, 1);
        p += __shfl_xor_sync(0xffffffffu, p, 2);
        p += __shfl_xor_sync(0xffffffffu, p, 4);
        p += __shfl_xor_sync(0xffffffffu, p, 8);
        p += __shfl_xor_sync(0xffffffffu, p, 16);
        float mn = fmaxf(m, p);
        float sc1 = __expf(m - mn);
        float sc2 = __expf(p - mn);
        s = s * sc1 + sc2;
        acc = fmaf(acc, sc1, sc2 * u);
        m = mn;
    }
    out[(size_t)node * COUT + lane] = acc / s + r2[(size_t)node * COUT + lane];
}

// ================= host =================
extern "C" void kernel_launch(void* const* d_in, const int* in_sizes, int n_in,
                              void* d_out, int out_size) {
    const float* x     = (const float*)d_in[0];
    const int*   src   = (const int*)  d_in[1];
    const int*   dst   = (const int*)  d_in[2];
    const float* W0    = (const float*)d_in[3];
    const float* a0    = (const float*)d_in[4];
    const float* W1    = (const float*)d_in[5];
    const float* a1    = (const float*)d_in[6];
    const float* W2    = (const float*)d_in[7];
    const float* a2    = (const float*)d_in[8];
    const float* Wres2 = (const float*)d_in[9];
    int E = in_sizes[1];
    if (E > EMAX) E = EMAX;

    float *f, *h0, *h1, *f2, *r2;
    __nv_bfloat16 *ahi, *alo, *bh0, *bl0, *bh1, *bl1, *bh2, *bl2;
    int *deg, *fill, *tmp, *bsum, *rowptr, *csrc;
    cudaGetSymbolAddress((void**)&f,    g_f);
    cudaGetSymbolAddress((void**)&h0,   g_h0);
    cudaGetSymbolAddress((void**)&h1,   g_h1);
    cudaGetSymbolAddress((void**)&f2,   g_f2);
    cudaGetSymbolAddress((void**)&r2,   g_r2);
    cudaGetSymbolAddress((void**)&ahi,  g_ahi);
    cudaGetSymbolAddress((void**)&alo,  g_alo);
    cudaGetSymbolAddress((void**)&bh0,  g_bh0);
    cudaGetSymbolAddress((void**)&bl0,  g_bl0);
    cudaGetSymbolAddress((void**)&bh1,  g_bh1);
    cudaGetSymbolAddress((void**)&bl1,  g_bl1);
    cudaGetSymbolAddress((void**)&bh2,  g_bh2);
    cudaGetSymbolAddress((void**)&bl2,  g_bl2);
    cudaGetSymbolAddress((void**)&deg,  g_deg);
    cudaGetSymbolAddress((void**)&fill, g_fill);
    cudaGetSymbolAddress((void**)&tmp,  g_tmp);
    cudaGetSymbolAddress((void**)&bsum, g_bsum);
    cudaGetSymbolAddress((void**)&rowptr, g_rowptr);
    cudaGetSymbolAddress((void**)&csrc, g_csrc);

    const int SMEM_BIG   = 3 * (16384 + 128 * 128);  // 98304
    const int SMEM_SMALL = 3 * (16384 + 64 * 128);   // 73728
    static int smem_set = 0;
    if (!smem_set) {
        cudaFuncSetAttribute((const void*)gemm_mma<128, 4, false>,
                             cudaFuncAttributeMaxDynamicSharedMemorySize, SMEM_BIG);
        cudaFuncSetAttribute((const void*)gemm_mma<64, 2, true>,
                             cudaFuncAttributeMaxDynamicSharedMemorySize, SMEM_SMALL);
        smem_set = 1;
    }

    const int TPB = 256;
    const int NB = (NNODES + 255) / 256;   // 196
    const int EB = (E + TPB - 1) / TPB;
    const int nodeWarpBlocks = (NNODES * 32 + TPB - 1) / TPB;
    const int splitBlocks = (MPAD * DIM + TPB - 1) / TPB;
    dim3 gemmGrid(2, MPAD / 128);
    dim3 gemmGridS(1, MPAD / 128);

    // ---- prep: splits + all weight transposes + CSR zero; big GEMM is launch #4 ----
    split_rows<<<splitBlocks, TPB>>>(x, ahi, alo, NNODES * DIM);                           // 1
    transpose_all<<<(147456 + TPB - 1) / TPB, TPB>>>(W0, W1, W2, Wres2,
                                                     bh0, bl0, bh1, bl1, bh2, bl2);        // 2
    zero_ints<<<NB, TPB>>>(deg, fill, NNODES);                                             // 3
    gemm_mma<128, 4, false><<<gemmGrid, TPB, SMEM_BIG>>>(ahi, alo, bh0, bl0, f, nullptr, NNODES); // 4

    // ---- CSR build ----
    hist_deg<<<EB, TPB>>>(dst, deg, E);
    scan_block<<<NB, TPB>>>(deg, tmp, bsum, NNODES);
    finalize_rowptr<<<NB, TPB>>>(tmp, bsum, rowptr, NNODES, NB);
    scatter_edges<<<EB, TPB>>>(src, dst, rowptr, fill, csrc, E);

    // ---- layer 0 edge phase ----
    gat_layer_h4<<<nodeWarpBlocks, TPB>>>(f, rowptr, csrc, a0, nullptr, h0, NNODES);

    // ---- layer 1 ----
    split_rows<<<splitBlocks, TPB>>>(h0, ahi, alo, NNODES * DIM);
    gemm_mma<128, 4, false><<<gemmGrid, TPB, SMEM_BIG>>>(ahi, alo, bh1, bl1, f, nullptr, NNODES);
    gat_layer_h4<<<nodeWarpBlocks, TPB>>>(f, rowptr, csrc, a1, h0, h1, NNODES);

    // ---- layer 2 ----
    split_rows<<<splitBlocks, TPB>>>(h1, ahi, alo, NNODES * DIM);
    gemm_mma<64, 2, true><<<gemmGridS, TPB, SMEM_SMALL>>>(ahi, alo, bh2, bl2, f2, r2, NNODES);
    gat_layer_h1<<<nodeWarpBlocks, TPB>>>(f2, rowptr, csrc, a2, r2, (float*)d_out, NNODES);
}